// round 8
// baseline (speedup 1.0000x reference)
#include <cuda_runtime.h>
#include <cstdint>
#include <cstddef>

// Problem dims (fixed by the dataset)
#define B_   16
#define N_   4096
#define S_   1024
#define C1_  256
#define C2_  256
#define K0_  512      // C1+C2
#define M0_  256
#define M1_  256
#define MTOT (B_*N_)  // 65536 rows (b*N+n)

// ---------------- scratch (static device globals; no cudaMalloc allowed) ----
__device__ float g_XT[(size_t)MTOT * K0_];        // [B*N, 512]  concat activations
__device__ float g_p2t[(size_t)B_ * S_ * C2_];    // [B, S, C2]  transposed points2
__device__ int   g_idx[(size_t)B_ * N_ * 3];
__device__ float g_w[(size_t)B_ * N_ * 3];
__device__ float g_y0[(size_t)MTOT * M0_];        // [B*N, 256] layer-0 pre/post BN (in place)
__device__ float g_y1[(size_t)MTOT * M1_];        // [B*N, 256] layer-1 pre-BN
__device__ float g_sum0[M0_], g_sq0[M0_], g_sum1[M1_], g_sq1[M1_];
__device__ float g_scale0[M0_], g_shift0[M0_], g_scale1[M1_], g_shift1[M1_];

// ---------------- packed f32x2 helpers (FFMA2 pipe) -------------------------
static __device__ __forceinline__ unsigned long long pk2(float lo, float hi) {
    unsigned long long r;
    asm("mov.b64 %0, {%1, %2};" : "=l"(r) : "f"(lo), "f"(hi));
    return r;
}
static __device__ __forceinline__ unsigned long long fma2(unsigned long long a,
                                                          unsigned long long b,
                                                          unsigned long long c) {
    unsigned long long d;
    asm("fma.rn.f32x2 %0, %1, %2, %3;" : "=l"(d) : "l"(a), "l"(b), "l"(c));
    return d;
}
static __device__ __forceinline__ void upk2(unsigned long long v, float& lo, float& hi) {
    asm("mov.b64 {%0, %1}, %2;" : "=f"(lo), "=f"(hi) : "l"(v));
}

// ---------------- kernel: zero BN-stat accumulators -------------------------
__global__ void zero_stats_kernel() {
    int t = threadIdx.x;          // 256 threads
    g_sum0[t] = 0.f; g_sq0[t] = 0.f;
    g_sum1[t] = 0.f; g_sq1[t] = 0.f;
}

// ---------------- kernel: transpose points1 [B,C1,N] -> XT[:, 0:256] --------
__global__ void transpose_p1_kernel(const float* __restrict__ p1) {
    __shared__ float tile[32][33];
    int b = blockIdx.z;
    int n0 = blockIdx.x * 32, c0 = blockIdx.y * 32;
    int tx = threadIdx.x, ty = threadIdx.y;
    const float* ip = p1 + (size_t)b * C1_ * N_;
    float* op = g_XT + (size_t)b * N_ * K0_;
#pragma unroll
    for (int i = 0; i < 4; i++) {
        int r = ty + i * 8;
        tile[r][tx] = ip[(size_t)(c0 + r) * N_ + n0 + tx];
    }
    __syncthreads();
#pragma unroll
    for (int i = 0; i < 4; i++) {
        int r = ty + i * 8;
        op[(size_t)(n0 + r) * K0_ + c0 + tx] = tile[tx][r];
    }
}

// ---------------- kernel: transpose points2 [B,C2,S] -> p2t [B,S,C2] --------
__global__ void transpose_p2_kernel(const float* __restrict__ p2) {
    __shared__ float tile[32][33];
    int b = blockIdx.z;
    int s0 = blockIdx.x * 32, c0 = blockIdx.y * 32;
    int tx = threadIdx.x, ty = threadIdx.y;
    const float* ip = p2 + (size_t)b * C2_ * S_;
    float* op = g_p2t + (size_t)b * S_ * C2_;
#pragma unroll
    for (int i = 0; i < 4; i++) {
        int r = ty + i * 8;
        tile[r][tx] = ip[(size_t)(c0 + r) * S_ + s0 + tx];
    }
    __syncthreads();
#pragma unroll
    for (int i = 0; i < 4; i++) {
        int r = ty + i * 8;
        op[(size_t)(s0 + r) * C2_ + c0 + tx] = tile[tx][r];
    }
}

// ---------------- kernel: 3-NN + inverse-distance weights -------------------
__global__ void knn_kernel(const float* __restrict__ xyz1,
                           const float* __restrict__ xyz2) {
    __shared__ float sx[S_], sy[S_], sz[S_], s2[S_];
    int b = blockIdx.y;
    const float* x2 = xyz2 + (size_t)b * 3 * S_;
    for (int j = threadIdx.x; j < S_; j += 128) {
        float a = x2[j], c = x2[S_ + j], d = x2[2 * S_ + j];
        sx[j] = a; sy[j] = c; sz[j] = d;
        s2[j] = a * a + c * c + d * d;
    }
    __syncthreads();

    int n = blockIdx.x * 128 + threadIdx.x;
    const float* x1 = xyz1 + (size_t)b * 3 * N_;
    float px = x1[n], py = x1[N_ + n], pz = x1[2 * N_ + n];
    float n1 = px * px + py * py + pz * pz;

    float d0 = 1e30f, d1 = 1e30f, d2 = 1e30f;
    int i0 = 0, i1 = 0, i2 = 0;
#pragma unroll 4
    for (int s = 0; s < S_; s++) {
        float dot = px * sx[s] + py * sy[s] + pz * sz[s];
        float d = n1 + s2[s] - 2.f * dot;   // same formula as reference
        if (d < d2) {
            if (d < d1) {
                d2 = d1; i2 = i1;
                if (d < d0) { d1 = d0; i1 = i0; d0 = d; i0 = s; }
                else        { d1 = d;  i1 = s; }
            } else { d2 = d; i2 = s; }
        }
    }
    float r0 = 1.f / (d0 + 1e-8f);
    float r1 = 1.f / (d1 + 1e-8f);
    float r2 = 1.f / (d2 + 1e-8f);
    float rs = r0 + r1 + r2;
    size_t base = ((size_t)b * N_ + n) * 3;
    g_idx[base] = i0; g_idx[base + 1] = i1; g_idx[base + 2] = i2;
    g_w[base] = r0 / rs; g_w[base + 1] = r1 / rs; g_w[base + 2] = r2 / rs;
}

// ---------------- kernel: weighted gather -> XT[:, 256:512] -----------------
// One warp per point n; coalesced float4 row reads from p2t (L2-resident).
__global__ void gather_kernel() {
    int b = blockIdx.y;
    int warp = threadIdx.x >> 5, lane = threadIdx.x & 31;
    int n = blockIdx.x * 8 + warp;
    size_t base = ((size_t)b * N_ + n) * 3;
    int i0 = g_idx[base], i1 = g_idx[base + 1], i2 = g_idx[base + 2];
    float w0 = g_w[base], w1 = g_w[base + 1], w2 = g_w[base + 2];
    const float4* r0 = (const float4*)(g_p2t + ((size_t)b * S_ + i0) * C2_);
    const float4* r1 = (const float4*)(g_p2t + ((size_t)b * S_ + i1) * C2_);
    const float4* r2 = (const float4*)(g_p2t + ((size_t)b * S_ + i2) * C2_);
    float4* dst = (float4*)(g_XT + ((size_t)b * N_ + n) * K0_ + C1_);
#pragma unroll
    for (int t = 0; t < 2; t++) {
        int c = lane + t * 32;                 // 64 float4 per 256-ch row
        float4 a = r0[c], bb = r1[c], cc = r2[c];
        float4 o;
        o.x = w0 * a.x + w1 * bb.x + w2 * cc.x;
        o.y = w0 * a.y + w1 * bb.y + w2 * cc.y;
        o.z = w0 * a.z + w1 * bb.z + w2 * cc.z;
        o.w = w0 * a.w + w1 * bb.w + w2 * cc.w;
        dst[c] = o;
    }
}

// ---------------- NT GEMM body: C[M,256] = A[M,K] * Bw[256,K]^T + bias ------
// Also accumulates per-output-channel sum / sumsq (BN training stats).
template <int KDIM>
static __device__ __forceinline__ void gemm_body(const float* __restrict__ A,
                                                 const float* __restrict__ Bw,
                                                 const float* __restrict__ bias,
                                                 float* __restrict__ C,
                                                 float* __restrict__ gsum,
                                                 float* __restrict__ gsq) {
    const int BK = 16;
    __shared__ float As[BK][128];
    __shared__ float Bs[BK][128];

    int m0 = blockIdx.x * 128;
    int n0 = blockIdx.y * 128;
    int tid = threadIdx.x;
    int tx = tid & 15, ty = tid >> 4;

    unsigned long long acc[8][4];
#pragma unroll
    for (int i = 0; i < 8; i++)
#pragma unroll
        for (int j = 0; j < 4; j++) acc[i][j] = 0ull;

    for (int kt = 0; kt < KDIM; kt += BK) {
#pragma unroll
        for (int h = 0; h < 2; h++) {
            int f = tid + h * 256;            // float4 id 0..511
            int row = f >> 2;
            int kc = (f & 3) * 4;
            float4 v = *(const float4*)(A + (size_t)(m0 + row) * KDIM + kt + kc);
            As[kc + 0][row] = v.x; As[kc + 1][row] = v.y;
            As[kc + 2][row] = v.z; As[kc + 3][row] = v.w;
            float4 u = *(const float4*)(Bw + (size_t)(n0 + row) * KDIM + kt + kc);
            Bs[kc + 0][row] = u.x; Bs[kc + 1][row] = u.y;
            Bs[kc + 2][row] = u.z; Bs[kc + 3][row] = u.w;
        }
        __syncthreads();
#pragma unroll
        for (int k = 0; k < BK; k++) {
            float4 a0 = *(const float4*)&As[k][ty * 8];
            float4 a1 = *(const float4*)&As[k][ty * 8 + 4];
            float4 b0 = *(const float4*)&Bs[k][tx * 8];
            float4 b1 = *(const float4*)&Bs[k][tx * 8 + 4];
            unsigned long long bp[4];
            bp[0] = pk2(b0.x, b0.y); bp[1] = pk2(b0.z, b0.w);
            bp[2] = pk2(b1.x, b1.y); bp[3] = pk2(b1.z, b1.w);
            float av[8] = {a0.x, a0.y, a0.z, a0.w, a1.x, a1.y, a1.z, a1.w};
#pragma unroll
            for (int i = 0; i < 8; i++) {
                unsigned long long aa = pk2(av[i], av[i]);
#pragma unroll
                for (int j = 0; j < 4; j++) acc[i][j] = fma2(aa, bp[j], acc[i][j]);
            }
        }
        __syncthreads();
    }

    // ---- epilogue: bias, store, per-channel stats ----
    float bv[8];
#pragma unroll
    for (int j = 0; j < 8; j++) bv[j] = bias[n0 + tx * 8 + j];

    float colsum[8], colsq[8];
#pragma unroll
    for (int j = 0; j < 8; j++) { colsum[j] = 0.f; colsq[j] = 0.f; }

#pragma unroll
    for (int i = 0; i < 8; i++) {
        float v[8];
#pragma unroll
        for (int j = 0; j < 4; j++) upk2(acc[i][j], v[2 * j], v[2 * j + 1]);
#pragma unroll
        for (int j = 0; j < 8; j++) {
            v[j] += bv[j];
            colsum[j] += v[j];
            colsq[j] += v[j] * v[j];
        }
        float4* out = (float4*)(C + (size_t)(m0 + ty * 8 + i) * 256 + n0 + tx * 8);
        out[0] = make_float4(v[0], v[1], v[2], v[3]);
        out[1] = make_float4(v[4], v[5], v[6], v[7]);
    }

    __syncthreads();                     // done with As as GEMM tiles
    float* ssum = &As[0][0];             // reuse smem: 128 + 128 floats
    float* ssq  = &As[0][0] + 128;
    if (tid < 128) { ssum[tid] = 0.f; ssq[tid] = 0.f; }
    __syncthreads();
#pragma unroll
    for (int j = 0; j < 8; j++) {
        atomicAdd(&ssum[tx * 8 + j], colsum[j]);
        atomicAdd(&ssq[tx * 8 + j], colsq[j]);
    }
    __syncthreads();
    if (tid < 128) {
        atomicAdd(&gsum[n0 + tid], ssum[tid]);
        atomicAdd(&gsq[n0 + tid], ssq[tid]);
    }
}

__global__ __launch_bounds__(256, 2)
void gemm1_kernel(const float* __restrict__ w0, const float* __restrict__ b0) {
    gemm_body<K0_>(g_XT, w0, b0, g_y0, g_sum0, g_sq0);
}
__global__ __launch_bounds__(256, 2)
void gemm2_kernel(const float* __restrict__ w1, const float* __restrict__ b1) {
    gemm_body<M0_>(g_y0, w1, b1, g_y1, g_sum1, g_sq1);
}

// ---------------- kernel: finalize BN stats -> scale/shift ------------------
__global__ void finalize0_kernel(const float* __restrict__ gamma,
                                 const float* __restrict__ beta) {
    int c = threadIdx.x;
    float cnt = (float)MTOT;
    float mean = g_sum0[c] / cnt;
    float var = g_sq0[c] / cnt - mean * mean;
    float inv = rsqrtf(var + 1e-5f);
    float sc = gamma[c] * inv;
    g_scale0[c] = sc;
    g_shift0[c] = beta[c] - mean * sc;
}
__global__ void finalize1_kernel(const float* __restrict__ gamma,
                                 const float* __restrict__ beta) {
    int c = threadIdx.x;
    float cnt = (float)MTOT;
    float mean = g_sum1[c] / cnt;
    float var = g_sq1[c] / cnt - mean * mean;
    float inv = rsqrtf(var + 1e-5f);
    float sc = gamma[c] * inv;
    g_scale1[c] = sc;
    g_shift1[c] = beta[c] - mean * sc;
}

// ---------------- kernel: BN + ReLU in place on g_y0 (layer 0) --------------
__global__ void bnrelu0_kernel() {
    size_t i4 = (size_t)blockIdx.x * 256 + threadIdx.x;   // float4 index
    float4* p = (float4*)g_y0;
    float4 v = p[i4];
    int c = ((int)(i4 & 63)) * 4;                          // 64 float4 per 256-ch row
    v.x = fmaxf(v.x * g_scale0[c + 0] + g_shift0[c + 0], 0.f);
    v.y = fmaxf(v.y * g_scale0[c + 1] + g_shift0[c + 1], 0.f);
    v.z = fmaxf(v.z * g_scale0[c + 2] + g_shift0[c + 2], 0.f);
    v.w = fmaxf(v.w * g_scale0[c + 3] + g_shift0[c + 3], 0.f);
    p[i4] = v;
}

// ---------------- kernel: BN + ReLU + transpose -> out [B, M1, N] -----------
__global__ void bnrelu1_transpose_kernel(float* __restrict__ out) {
    __shared__ float tile[32][33];
    int b = blockIdx.z;
    int n0 = blockIdx.x * 32, o0 = blockIdx.y * 32;
    int tx = threadIdx.x, ty = threadIdx.y;
    float sc = g_scale1[o0 + tx];
    float sh = g_shift1[o0 + tx];
    const float* ip = g_y1 + (size_t)b * N_ * M1_;
#pragma unroll
    for (int i = 0; i < 4; i++) {
        int r = ty + i * 8;
        float v = ip[(size_t)(n0 + r) * M1_ + o0 + tx];
        tile[r][tx] = fmaxf(v * sc + sh, 0.f);
    }
    __syncthreads();
    float* op = out + (size_t)b * M1_ * N_;
#pragma unroll
    for (int i = 0; i < 4; i++) {
        int r = ty + i * 8;
        op[(size_t)(o0 + r) * N_ + n0 + tx] = tile[tx][r];
    }
}

// ---------------- launch --------------------------------------------------
extern "C" void kernel_launch(void* const* d_in, const int* in_sizes, int n_in,
                              void* d_out, int out_size) {
    const float* xyz1 = (const float*)d_in[0];
    const float* xyz2 = (const float*)d_in[1];
    const float* p1   = (const float*)d_in[2];
    const float* p2   = (const float*)d_in[3];
    const float* w0   = (const float*)d_in[4];
    const float* b0   = (const float*)d_in[5];
    const float* g0   = (const float*)d_in[6];
    const float* be0  = (const float*)d_in[7];
    const float* w1   = (const float*)d_in[8];
    const float* b1   = (const float*)d_in[9];
    const float* g1   = (const float*)d_in[10];
    const float* be1  = (const float*)d_in[11];
    float* out = (float*)d_out;

    zero_stats_kernel<<<1, 256>>>();
    transpose_p1_kernel<<<dim3(N_ / 32, C1_ / 32, B_), dim3(32, 8)>>>(p1);
    transpose_p2_kernel<<<dim3(S_ / 32, C2_ / 32, B_), dim3(32, 8)>>>(p2);
    knn_kernel<<<dim3(N_ / 128, B_), 128>>>(xyz1, xyz2);
    gather_kernel<<<dim3(N_ / 8, B_), 256>>>();

    gemm1_kernel<<<dim3(MTOT / 128, M0_ / 128), 256>>>(w0, b0);
    finalize0_kernel<<<1, 256>>>(g0, be0);
    bnrelu0_kernel<<<(unsigned)((size_t)MTOT * M0_ / 4 / 256), 256>>>();

    gemm2_kernel<<<dim3(MTOT / 128, M1_ / 128), 256>>>(w1, b1);
    finalize1_kernel<<<1, 256>>>(g1, be1);
    bnrelu1_transpose_kernel<<<dim3(N_ / 32, M1_ / 32, B_), dim3(32, 8)>>>(out);
}

// round 9
// speedup vs baseline: 1.0009x; 1.0009x over previous
#include <cuda_runtime.h>
#include <cstdint>
#include <cstddef>

// Problem dims (fixed by the dataset)
#define B_   16
#define N_   4096
#define S_   1024
#define C1_  256
#define C2_  256
#define K0_  512      // C1+C2
#define M0_  256
#define M1_  256
#define MTOT (B_*N_)  // 65536 rows (b*N+n)

// ---------------- scratch (static device globals; no cudaMalloc allowed) ----
__device__ float g_XT[(size_t)MTOT * K0_];        // [B*N, 512]  concat activations
__device__ float g_p2t[(size_t)B_ * S_ * C2_];    // [B, S, C2]  transposed points2
__device__ int   g_idx[(size_t)B_ * N_ * 3];
__device__ float g_w[(size_t)B_ * N_ * 3];
__device__ float g_y0[(size_t)MTOT * M0_];        // [B*N, 256] layer-0 pre/post BN (in place)
__device__ float g_y1[(size_t)MTOT * M1_];        // [B*N, 256] layer-1 pre-BN
__device__ float g_sum0[M0_], g_sq0[M0_], g_sum1[M1_], g_sq1[M1_];
__device__ float g_scale0[M0_], g_shift0[M0_], g_scale1[M1_], g_shift1[M1_];

// ---------------- packed f32x2 helpers (FFMA2 pipe) -------------------------
static __device__ __forceinline__ unsigned long long pk2(float lo, float hi) {
    unsigned long long r;
    asm("mov.b64 %0, {%1, %2};" : "=l"(r) : "f"(lo), "f"(hi));
    return r;
}
static __device__ __forceinline__ unsigned long long fma2(unsigned long long a,
                                                          unsigned long long b,
                                                          unsigned long long c) {
    unsigned long long d;
    asm("fma.rn.f32x2 %0, %1, %2, %3;" : "=l"(d) : "l"(a), "l"(b), "l"(c));
    return d;
}
static __device__ __forceinline__ void upk2(unsigned long long v, float& lo, float& hi) {
    asm("mov.b64 {%0, %1}, %2;" : "=f"(lo), "=f"(hi) : "l"(v));
}

// ---------------- kernel: zero BN-stat accumulators -------------------------
__global__ void zero_stats_kernel() {
    int t = threadIdx.x;          // 256 threads
    g_sum0[t] = 0.f; g_sq0[t] = 0.f;
    g_sum1[t] = 0.f; g_sq1[t] = 0.f;
}

// ---------------- kernel: transpose points1 [B,C1,N] -> XT[:, 0:256] --------
__global__ void transpose_p1_kernel(const float* __restrict__ p1) {
    __shared__ float tile[32][33];
    int b = blockIdx.z;
    int n0 = blockIdx.x * 32, c0 = blockIdx.y * 32;
    int tx = threadIdx.x, ty = threadIdx.y;
    const float* ip = p1 + (size_t)b * C1_ * N_;
    float* op = g_XT + (size_t)b * N_ * K0_;
#pragma unroll
    for (int i = 0; i < 4; i++) {
        int r = ty + i * 8;
        tile[r][tx] = ip[(size_t)(c0 + r) * N_ + n0 + tx];
    }
    __syncthreads();
#pragma unroll
    for (int i = 0; i < 4; i++) {
        int r = ty + i * 8;
        op[(size_t)(n0 + r) * K0_ + c0 + tx] = tile[tx][r];
    }
}

// ---------------- kernel: transpose points2 [B,C2,S] -> p2t [B,S,C2] --------
__global__ void transpose_p2_kernel(const float* __restrict__ p2) {
    __shared__ float tile[32][33];
    int b = blockIdx.z;
    int s0 = blockIdx.x * 32, c0 = blockIdx.y * 32;
    int tx = threadIdx.x, ty = threadIdx.y;
    const float* ip = p2 + (size_t)b * C2_ * S_;
    float* op = g_p2t + (size_t)b * S_ * C2_;
#pragma unroll
    for (int i = 0; i < 4; i++) {
        int r = ty + i * 8;
        tile[r][tx] = ip[(size_t)(c0 + r) * S_ + s0 + tx];
    }
    __syncthreads();
#pragma unroll
    for (int i = 0; i < 4; i++) {
        int r = ty + i * 8;
        op[(size_t)(s0 + r) * C2_ + c0 + tx] = tile[tx][r];
    }
}

// ---------------- kernel: 3-NN + inverse-distance weights -------------------
__global__ void knn_kernel(const float* __restrict__ xyz1,
                           const float* __restrict__ xyz2) {
    __shared__ float sx[S_], sy[S_], sz[S_], s2[S_];
    int b = blockIdx.y;
    const float* x2 = xyz2 + (size_t)b * 3 * S_;
    for (int j = threadIdx.x; j < S_; j += 128) {
        float a = x2[j], c = x2[S_ + j], d = x2[2 * S_ + j];
        sx[j] = a; sy[j] = c; sz[j] = d;
        s2[j] = a * a + c * c + d * d;
    }
    __syncthreads();

    int n = blockIdx.x * 128 + threadIdx.x;
    const float* x1 = xyz1 + (size_t)b * 3 * N_;
    float px = x1[n], py = x1[N_ + n], pz = x1[2 * N_ + n];
    float n1 = px * px + py * py + pz * pz;

    float d0 = 1e30f, d1 = 1e30f, d2 = 1e30f;
    int i0 = 0, i1 = 0, i2 = 0;
#pragma unroll 4
    for (int s = 0; s < S_; s++) {
        float dot = px * sx[s] + py * sy[s] + pz * sz[s];
        float d = n1 + s2[s] - 2.f * dot;   // same formula as reference
        if (d < d2) {
            if (d < d1) {
                d2 = d1; i2 = i1;
                if (d < d0) { d1 = d0; i1 = i0; d0 = d; i0 = s; }
                else        { d1 = d;  i1 = s; }
            } else { d2 = d; i2 = s; }
        }
    }
    float r0 = 1.f / (d0 + 1e-8f);
    float r1 = 1.f / (d1 + 1e-8f);
    float r2 = 1.f / (d2 + 1e-8f);
    float rs = r0 + r1 + r2;
    size_t base = ((size_t)b * N_ + n) * 3;
    g_idx[base] = i0; g_idx[base + 1] = i1; g_idx[base + 2] = i2;
    g_w[base] = r0 / rs; g_w[base + 1] = r1 / rs; g_w[base + 2] = r2 / rs;
}

// ---------------- kernel: weighted gather -> XT[:, 256:512] -----------------
// One warp per point n; coalesced float4 row reads from p2t (L2-resident).
__global__ void gather_kernel() {
    int b = blockIdx.y;
    int warp = threadIdx.x >> 5, lane = threadIdx.x & 31;
    int n = blockIdx.x * 8 + warp;
    size_t base = ((size_t)b * N_ + n) * 3;
    int i0 = g_idx[base], i1 = g_idx[base + 1], i2 = g_idx[base + 2];
    float w0 = g_w[base], w1 = g_w[base + 1], w2 = g_w[base + 2];
    const float4* r0 = (const float4*)(g_p2t + ((size_t)b * S_ + i0) * C2_);
    const float4* r1 = (const float4*)(g_p2t + ((size_t)b * S_ + i1) * C2_);
    const float4* r2 = (const float4*)(g_p2t + ((size_t)b * S_ + i2) * C2_);
    float4* dst = (float4*)(g_XT + ((size_t)b * N_ + n) * K0_ + C1_);
#pragma unroll
    for (int t = 0; t < 2; t++) {
        int c = lane + t * 32;                 // 64 float4 per 256-ch row
        float4 a = r0[c], bb = r1[c], cc = r2[c];
        float4 o;
        o.x = w0 * a.x + w1 * bb.x + w2 * cc.x;
        o.y = w0 * a.y + w1 * bb.y + w2 * cc.y;
        o.z = w0 * a.z + w1 * bb.z + w2 * cc.z;
        o.w = w0 * a.w + w1 * bb.w + w2 * cc.w;
        dst[c] = o;
    }
}

// ---------------- NT GEMM body: C[M,256] = A[M,K] * Bw[256,K]^T + bias ------
// Also accumulates per-output-channel sum / sumsq (BN training stats).
template <int KDIM>
static __device__ __forceinline__ void gemm_body(const float* __restrict__ A,
                                                 const float* __restrict__ Bw,
                                                 const float* __restrict__ bias,
                                                 float* __restrict__ C,
                                                 float* __restrict__ gsum,
                                                 float* __restrict__ gsq) {
    const int BK = 16;
    __shared__ float As[BK][128];
    __shared__ float Bs[BK][128];

    int m0 = blockIdx.x * 128;
    int n0 = blockIdx.y * 128;
    int tid = threadIdx.x;
    int tx = tid & 15, ty = tid >> 4;

    unsigned long long acc[8][4];
#pragma unroll
    for (int i = 0; i < 8; i++)
#pragma unroll
        for (int j = 0; j < 4; j++) acc[i][j] = 0ull;

    for (int kt = 0; kt < KDIM; kt += BK) {
#pragma unroll
        for (int h = 0; h < 2; h++) {
            int f = tid + h * 256;            // float4 id 0..511
            int row = f >> 2;
            int kc = (f & 3) * 4;
            float4 v = *(const float4*)(A + (size_t)(m0 + row) * KDIM + kt + kc);
            As[kc + 0][row] = v.x; As[kc + 1][row] = v.y;
            As[kc + 2][row] = v.z; As[kc + 3][row] = v.w;
            float4 u = *(const float4*)(Bw + (size_t)(n0 + row) * KDIM + kt + kc);
            Bs[kc + 0][row] = u.x; Bs[kc + 1][row] = u.y;
            Bs[kc + 2][row] = u.z; Bs[kc + 3][row] = u.w;
        }
        __syncthreads();
#pragma unroll
        for (int k = 0; k < BK; k++) {
            float4 a0 = *(const float4*)&As[k][ty * 8];
            float4 a1 = *(const float4*)&As[k][ty * 8 + 4];
            float4 b0 = *(const float4*)&Bs[k][tx * 8];
            float4 b1 = *(const float4*)&Bs[k][tx * 8 + 4];
            unsigned long long bp[4];
            bp[0] = pk2(b0.x, b0.y); bp[1] = pk2(b0.z, b0.w);
            bp[2] = pk2(b1.x, b1.y); bp[3] = pk2(b1.z, b1.w);
            float av[8] = {a0.x, a0.y, a0.z, a0.w, a1.x, a1.y, a1.z, a1.w};
#pragma unroll
            for (int i = 0; i < 8; i++) {
                unsigned long long aa = pk2(av[i], av[i]);
#pragma unroll
                for (int j = 0; j < 4; j++) acc[i][j] = fma2(aa, bp[j], acc[i][j]);
            }
        }
        __syncthreads();
    }

    // ---- epilogue: bias, store, per-channel stats ----
    float bv[8];
#pragma unroll
    for (int j = 0; j < 8; j++) bv[j] = bias[n0 + tx * 8 + j];

    float colsum[8], colsq[8];
#pragma unroll
    for (int j = 0; j < 8; j++) { colsum[j] = 0.f; colsq[j] = 0.f; }

#pragma unroll
    for (int i = 0; i < 8; i++) {
        float v[8];
#pragma unroll
        for (int j = 0; j < 4; j++) upk2(acc[i][j], v[2 * j], v[2 * j + 1]);
#pragma unroll
        for (int j = 0; j < 8; j++) {
            v[j] += bv[j];
            colsum[j] += v[j];
            colsq[j] += v[j] * v[j];
        }
        float4* out = (float4*)(C + (size_t)(m0 + ty * 8 + i) * 256 + n0 + tx * 8);
        out[0] = make_float4(v[0], v[1], v[2], v[3]);
        out[1] = make_float4(v[4], v[5], v[6], v[7]);
    }

    __syncthreads();                     // done with As as GEMM tiles
    float* ssum = &As[0][0];             // reuse smem: 128 + 128 floats
    float* ssq  = &As[0][0] + 128;
    if (tid < 128) { ssum[tid] = 0.f; ssq[tid] = 0.f; }
    __syncthreads();
#pragma unroll
    for (int j = 0; j < 8; j++) {
        atomicAdd(&ssum[tx * 8 + j], colsum[j]);
        atomicAdd(&ssq[tx * 8 + j], colsq[j]);
    }
    __syncthreads();
    if (tid < 128) {
        atomicAdd(&gsum[n0 + tid], ssum[tid]);
        atomicAdd(&gsq[n0 + tid], ssq[tid]);
    }
}

__global__ __launch_bounds__(256, 2)
void gemm1_kernel(const float* __restrict__ w0, const float* __restrict__ b0) {
    gemm_body<K0_>(g_XT, w0, b0, g_y0, g_sum0, g_sq0);
}
__global__ __launch_bounds__(256, 2)
void gemm2_kernel(const float* __restrict__ w1, const float* __restrict__ b1) {
    gemm_body<M0_>(g_y0, w1, b1, g_y1, g_sum1, g_sq1);
}

// ---------------- kernel: finalize BN stats -> scale/shift ------------------
__global__ void finalize0_kernel(const float* __restrict__ gamma,
                                 const float* __restrict__ beta) {
    int c = threadIdx.x;
    float cnt = (float)MTOT;
    float mean = g_sum0[c] / cnt;
    float var = g_sq0[c] / cnt - mean * mean;
    float inv = rsqrtf(var + 1e-5f);
    float sc = gamma[c] * inv;
    g_scale0[c] = sc;
    g_shift0[c] = beta[c] - mean * sc;
}
__global__ void finalize1_kernel(const float* __restrict__ gamma,
                                 const float* __restrict__ beta) {
    int c = threadIdx.x;
    float cnt = (float)MTOT;
    float mean = g_sum1[c] / cnt;
    float var = g_sq1[c] / cnt - mean * mean;
    float inv = rsqrtf(var + 1e-5f);
    float sc = gamma[c] * inv;
    g_scale1[c] = sc;
    g_shift1[c] = beta[c] - mean * sc;
}

// ---------------- kernel: BN + ReLU in place on g_y0 (layer 0) --------------
__global__ void bnrelu0_kernel() {
    size_t i4 = (size_t)blockIdx.x * 256 + threadIdx.x;   // float4 index
    float4* p = (float4*)g_y0;
    float4 v = p[i4];
    int c = ((int)(i4 & 63)) * 4;                          // 64 float4 per 256-ch row
    v.x = fmaxf(v.x * g_scale0[c + 0] + g_shift0[c + 0], 0.f);
    v.y = fmaxf(v.y * g_scale0[c + 1] + g_shift0[c + 1], 0.f);
    v.z = fmaxf(v.z * g_scale0[c + 2] + g_shift0[c + 2], 0.f);
    v.w = fmaxf(v.w * g_scale0[c + 3] + g_shift0[c + 3], 0.f);
    p[i4] = v;
}

// ---------------- kernel: BN + ReLU + transpose -> out [B, M1, N] -----------
__global__ void bnrelu1_transpose_kernel(float* __restrict__ out) {
    __shared__ float tile[32][33];
    int b = blockIdx.z;
    int n0 = blockIdx.x * 32, o0 = blockIdx.y * 32;
    int tx = threadIdx.x, ty = threadIdx.y;
    float sc = g_scale1[o0 + tx];
    float sh = g_shift1[o0 + tx];
    const float* ip = g_y1 + (size_t)b * N_ * M1_;
#pragma unroll
    for (int i = 0; i < 4; i++) {
        int r = ty + i * 8;
        float v = ip[(size_t)(n0 + r) * M1_ + o0 + tx];
        tile[r][tx] = fmaxf(v * sc + sh, 0.f);
    }
    __syncthreads();
    float* op = out + (size_t)b * M1_ * N_;
#pragma unroll
    for (int i = 0; i < 4; i++) {
        int r = ty + i * 8;
        op[(size_t)(o0 + r) * N_ + n0 + tx] = tile[tx][r];
    }
}

// ---------------- launch --------------------------------------------------
extern "C" void kernel_launch(void* const* d_in, const int* in_sizes, int n_in,
                              void* d_out, int out_size) {
    const float* xyz1 = (const float*)d_in[0];
    const float* xyz2 = (const float*)d_in[1];
    const float* p1   = (const float*)d_in[2];
    const float* p2   = (const float*)d_in[3];
    const float* w0   = (const float*)d_in[4];
    const float* b0   = (const float*)d_in[5];
    const float* g0   = (const float*)d_in[6];
    const float* be0  = (const float*)d_in[7];
    const float* w1   = (const float*)d_in[8];
    const float* b1   = (const float*)d_in[9];
    const float* g1   = (const float*)d_in[10];
    const float* be1  = (const float*)d_in[11];
    float* out = (float*)d_out;

    zero_stats_kernel<<<1, 256>>>();
    transpose_p1_kernel<<<dim3(N_ / 32, C1_ / 32, B_), dim3(32, 8)>>>(p1);
    transpose_p2_kernel<<<dim3(S_ / 32, C2_ / 32, B_), dim3(32, 8)>>>(p2);
    knn_kernel<<<dim3(N_ / 128, B_), 128>>>(xyz1, xyz2);
    gather_kernel<<<dim3(N_ / 8, B_), 256>>>();

    gemm1_kernel<<<dim3(MTOT / 128, M0_ / 128), 256>>>(w0, b0);
    finalize0_kernel<<<1, 256>>>(g0, be0);
    bnrelu0_kernel<<<(unsigned)((size_t)MTOT * M0_ / 4 / 256), 256>>>();

    gemm2_kernel<<<dim3(MTOT / 128, M1_ / 128), 256>>>(w1, b1);
    finalize1_kernel<<<1, 256>>>(g1, be1);
    bnrelu1_transpose_kernel<<<dim3(N_ / 32, M1_ / 32, B_), dim3(32, 8)>>>(out);
}

// round 12
// speedup vs baseline: 1.6067x; 1.6052x over previous
#include <cuda_runtime.h>
#include <cuda_bf16.h>
#include <cstdint>
#include <cstddef>

// Problem dims (fixed by the dataset)
#define B_   16
#define N_   4096
#define S_   1024
#define C1_  256
#define C2_  256
#define K0_  512      // C1+C2
#define M0_  256
#define M1_  256
#define MTOT (B_*N_)  // 65536 rows (b*N+n)

// ---------------- scratch (static device globals; no cudaMalloc allowed) ----
__device__ __align__(16) __nv_bfloat16 g_Ahi[(size_t)MTOT * K0_];   // 64 MB
__device__ __align__(16) __nv_bfloat16 g_Alo[(size_t)MTOT * K0_];   // 64 MB
__device__ __align__(16) __nv_bfloat16 g_Zhi[(size_t)MTOT * M0_];   // 32 MB (layer-1 input)
__device__ __align__(16) __nv_bfloat16 g_Zlo[(size_t)MTOT * M0_];   // 32 MB
__device__ __align__(16) __nv_bfloat16 g_W0hi[(size_t)M0_ * K0_], g_W0lo[(size_t)M0_ * K0_];
__device__ __align__(16) __nv_bfloat16 g_W1hi[(size_t)M1_ * M0_], g_W1lo[(size_t)M1_ * M0_];
__device__ float g_p2t[(size_t)B_ * S_ * C2_];    // [B, S, C2]  transposed points2
__device__ int   g_idx[(size_t)B_ * N_ * 3];
__device__ float g_w[(size_t)B_ * N_ * 3];
__device__ float g_y0[(size_t)MTOT * M0_];        // layer-0 pre-BN fp32
__device__ float g_y1[(size_t)MTOT * M1_];        // layer-1 pre-BN fp32
__device__ float g_sum0[M0_], g_sq0[M0_], g_sum1[M1_], g_sq1[M1_];
__device__ float g_scale0[M0_], g_shift0[M0_], g_scale1[M1_], g_shift1[M1_];

// ---------------- small helpers ---------------------------------------------
static __device__ __forceinline__ uint32_t sm32(const void* p) {
    return (uint32_t)__cvta_generic_to_shared(p);
}
static __device__ __forceinline__ void split_bf(float v, float& hf, float& lf) {
    __nv_bfloat16 h = __float2bfloat16_rn(v);
    hf = __bfloat162float(h);
    lf = v - hf;
}
static __device__ __forceinline__ uint32_t packbf(float a, float b) {
    __nv_bfloat162 t = __floats2bfloat162_rn(a, b);
    return *reinterpret_cast<uint32_t*>(&t);
}
static __device__ __forceinline__ void cpa16(uint32_t dst, const void* src) {
    asm volatile("cp.async.cg.shared.global [%0], [%1], 16;" :: "r"(dst), "l"(src));
}
static __device__ __forceinline__ void cp_commit() {
    asm volatile("cp.async.commit_group;" ::: "memory");
}
template <int n>
static __device__ __forceinline__ void cp_wait() {
    asm volatile("cp.async.wait_group %0;" :: "n"(n) : "memory");
}
// ldmatrix x4 (b16, non-transposed)
static __device__ __forceinline__ void ldmx4(uint32_t r[4], uint32_t addr) {
    asm volatile("ldmatrix.sync.aligned.m8n8.x4.shared.b16 {%0,%1,%2,%3}, [%4];"
                 : "=r"(r[0]), "=r"(r[1]), "=r"(r[2]), "=r"(r[3]) : "r"(addr));
}
// HMMA m16n8k16 bf16 -> f32 accumulate (base sm_80+ PTX, legal on compute_103)
static __device__ __forceinline__ void mma16816(float c[4], const uint32_t a[4],
                                                const uint32_t b[2]) {
    asm volatile(
        "mma.sync.aligned.m16n8k16.row.col.f32.bf16.bf16.f32 "
        "{%0,%1,%2,%3}, {%4,%5,%6,%7}, {%8,%9}, {%0,%1,%2,%3};"
        : "+f"(c[0]), "+f"(c[1]), "+f"(c[2]), "+f"(c[3])
        : "r"(a[0]), "r"(a[1]), "r"(a[2]), "r"(a[3]), "r"(b[0]), "r"(b[1]));
}
// swizzle for 32B rows (8-row atom spans 256B): XOR bit4 with bit7
static __device__ __forceinline__ uint32_t swz(uint32_t off) {
    return off ^ ((off >> 3) & 0x10);
}

// ---------------- kernel: zero BN-stat accumulators -------------------------
__global__ void zero_stats_kernel() {
    int t = threadIdx.x;          // 256 threads
    g_sum0[t] = 0.f; g_sq0[t] = 0.f;
    g_sum1[t] = 0.f; g_sq1[t] = 0.f;
}

// ---------------- kernels: fp32 weights -> bf16 hi/lo (globals in dev code) -
__global__ void convw0_kernel(const float* __restrict__ w) {
    int i = blockIdx.x * 256 + threadIdx.x;
    if (i < M0_ * K0_) {
        float v = w[i], hf, lf;
        split_bf(v, hf, lf);
        g_W0hi[i] = __float2bfloat16_rn(hf);
        g_W0lo[i] = __float2bfloat16_rn(lf);
    }
}
__global__ void convw1_kernel(const float* __restrict__ w) {
    int i = blockIdx.x * 256 + threadIdx.x;
    if (i < M1_ * M0_) {
        float v = w[i], hf, lf;
        split_bf(v, hf, lf);
        g_W1hi[i] = __float2bfloat16_rn(hf);
        g_W1lo[i] = __float2bfloat16_rn(lf);
    }
}

// ---------------- kernel: transpose points1 [B,C1,N] -> Ahi/Alo[:, 0:256] ---
__global__ void transpose_p1_kernel(const float* __restrict__ p1) {
    __shared__ float tile[32][33];
    int b = blockIdx.z;
    int n0 = blockIdx.x * 32, c0 = blockIdx.y * 32;
    int tx = threadIdx.x, ty = threadIdx.y;
    const float* ip = p1 + (size_t)b * C1_ * N_;
#pragma unroll
    for (int i = 0; i < 4; i++) {
        int r = ty + i * 8;
        tile[r][tx] = ip[(size_t)(c0 + r) * N_ + n0 + tx];
    }
    __syncthreads();
    size_t rb = (size_t)b * N_ * K0_;
#pragma unroll
    for (int i = 0; i < 4; i++) {
        int r = ty + i * 8;
        float v = tile[tx][r], hf, lf;
        split_bf(v, hf, lf);
        size_t e = rb + (size_t)(n0 + r) * K0_ + c0 + tx;
        g_Ahi[e] = __float2bfloat16_rn(hf);
        g_Alo[e] = __float2bfloat16_rn(lf);
    }
}

// ---------------- kernel: transpose points2 [B,C2,S] -> p2t [B,S,C2] --------
__global__ void transpose_p2_kernel(const float* __restrict__ p2) {
    __shared__ float tile[32][33];
    int b = blockIdx.z;
    int s0 = blockIdx.x * 32, c0 = blockIdx.y * 32;
    int tx = threadIdx.x, ty = threadIdx.y;
    const float* ip = p2 + (size_t)b * C2_ * S_;
    float* op = g_p2t + (size_t)b * S_ * C2_;
#pragma unroll
    for (int i = 0; i < 4; i++) {
        int r = ty + i * 8;
        tile[r][tx] = ip[(size_t)(c0 + r) * S_ + s0 + tx];
    }
    __syncthreads();
#pragma unroll
    for (int i = 0; i < 4; i++) {
        int r = ty + i * 8;
        op[(size_t)(s0 + r) * C2_ + c0 + tx] = tile[tx][r];
    }
}

// ---------------- kernel: 3-NN, 4 independent chains for ILP ----------------
__global__ void knn_kernel(const float* __restrict__ xyz1,
                           const float* __restrict__ xyz2) {
    __shared__ float4 s4[S_];
    int b = blockIdx.y;
    const float* x2 = xyz2 + (size_t)b * 3 * S_;
    for (int j = threadIdx.x; j < S_; j += 128) {
        float a = x2[j], c = x2[S_ + j], d = x2[2 * S_ + j];
        s4[j] = make_float4(a, c, d, a * a + c * c + d * d);
    }
    __syncthreads();

    int n = blockIdx.x * 128 + threadIdx.x;
    const float* x1 = xyz1 + (size_t)b * 3 * N_;
    float px = x1[n], py = x1[N_ + n], pz = x1[2 * N_ + n];
    float n1 = px * px + py * py + pz * pz;

    float cd0[4], cd1[4], cd2[4];
    int   ci0[4], ci1[4], ci2[4];
#pragma unroll
    for (int c = 0; c < 4; c++) {
        cd0[c] = cd1[c] = cd2[c] = 1e30f;
        ci0[c] = ci1[c] = ci2[c] = 0;
    }
    for (int t = 0; t < 256; t++) {
#pragma unroll
        for (int c = 0; c < 4; c++) {
            int s = t + c * 256;
            float4 w = s4[s];
            float dot = px * w.x + py * w.y + pz * w.z;
            float d = n1 + w.w - 2.f * dot;
            if (d < cd2[c]) {
                if (d < cd1[c]) {
                    cd2[c] = cd1[c]; ci2[c] = ci1[c];
                    if (d < cd0[c]) { cd1[c] = cd0[c]; ci1[c] = ci0[c]; cd0[c] = d; ci0[c] = s; }
                    else            { cd1[c] = d;      ci1[c] = s; }
                } else { cd2[c] = d; ci2[c] = s; }
            }
        }
    }
    // merge 12 candidates
    float d0 = 1e30f, d1 = 1e30f, d2 = 1e30f;
    int i0 = 0, i1 = 0, i2 = 0;
    auto ins = [&](float d, int i) {
        if (d < d2) {
            if (d < d1) {
                d2 = d1; i2 = i1;
                if (d < d0) { d1 = d0; i1 = i0; d0 = d; i0 = i; }
                else        { d1 = d;  i1 = i; }
            } else { d2 = d; i2 = i; }
        }
    };
#pragma unroll
    for (int c = 0; c < 4; c++) { ins(cd0[c], ci0[c]); ins(cd1[c], ci1[c]); ins(cd2[c], ci2[c]); }

    float r0 = 1.f / (d0 + 1e-8f);
    float r1 = 1.f / (d1 + 1e-8f);
    float r2 = 1.f / (d2 + 1e-8f);
    float rs = r0 + r1 + r2;
    size_t base = ((size_t)b * N_ + n) * 3;
    g_idx[base] = i0; g_idx[base + 1] = i1; g_idx[base + 2] = i2;
    g_w[base] = r0 / rs; g_w[base + 1] = r1 / rs; g_w[base + 2] = r2 / rs;
}

// ---------------- kernel: weighted gather -> Ahi/Alo[:, 256:512] ------------
__global__ void gather_kernel() {
    int b = blockIdx.y;
    int warp = threadIdx.x >> 5, lane = threadIdx.x & 31;
    int n = blockIdx.x * 8 + warp;
    size_t base = ((size_t)b * N_ + n) * 3;
    int i0 = g_idx[base], i1 = g_idx[base + 1], i2 = g_idx[base + 2];
    float w0 = g_w[base], w1 = g_w[base + 1], w2 = g_w[base + 2];
    const float4* r0 = (const float4*)(g_p2t + ((size_t)b * S_ + i0) * C2_);
    const float4* r1 = (const float4*)(g_p2t + ((size_t)b * S_ + i1) * C2_);
    const float4* r2 = (const float4*)(g_p2t + ((size_t)b * S_ + i2) * C2_);
    size_t rowe = ((size_t)b * N_ + n) * K0_ + C1_;
#pragma unroll
    for (int t = 0; t < 2; t++) {
        int c = lane + t * 32;                 // 64 float4 per 256-ch half
        float4 a = r0[c], bb = r1[c], cc = r2[c];
        float4 o;
        o.x = w0 * a.x + w1 * bb.x + w2 * cc.x;
        o.y = w0 * a.y + w1 * bb.y + w2 * cc.y;
        o.z = w0 * a.z + w1 * bb.z + w2 * cc.z;
        o.w = w0 * a.w + w1 * bb.w + w2 * cc.w;
        float hx, lx, hy, ly, hz, lz, hw, lw;
        split_bf(o.x, hx, lx); split_bf(o.y, hy, ly);
        split_bf(o.z, hz, lz); split_bf(o.w, hw, lw);
        size_t e = rowe + 4 * c;
        *reinterpret_cast<uint2*>(reinterpret_cast<char*>(g_Ahi) + e * 2) =
            make_uint2(packbf(hx, hy), packbf(hz, hw));
        *reinterpret_cast<uint2*>(reinterpret_cast<char*>(g_Alo) + e * 2) =
            make_uint2(packbf(lx, ly), packbf(lz, lw));
    }
}

// ---------------- HMMA 3xBF16 GEMM: C[M,256] = A[M,K] * W[256,K]^T + bias ----
// CTA tile 128x128, 8 warps (2x4), warp tile 64x32, BK=16, 3-stage cp.async.
// Accumulates per-output-channel sum/sumsq (BN training stats).
template <int KDIM>
static __device__ __forceinline__ void gemm_body(
    const __nv_bfloat16* __restrict__ Ah, const __nv_bfloat16* __restrict__ Al,
    const __nv_bfloat16* __restrict__ Wh, const __nv_bfloat16* __restrict__ Wl,
    const float* __restrict__ bias, float* __restrict__ C,
    float* __restrict__ gsum, float* __restrict__ gsq) {
    constexpr int NC = KDIM / 16;              // 32 or 16 k-steps
    __shared__ __align__(1024) char smem[3 * 16384];   // 3 stages x (Ah|Al|Wh|Wl 4KB each)

    int tid = threadIdx.x, lane = tid & 31, wid = tid >> 5;
    int wm = wid & 1, wn = wid >> 1;           // 2 x 4 warp grid
    int m0 = blockIdx.x * 128, n0 = blockIdx.y * 128;

    const char* pAh = (const char*)Ah;
    const char* pAl = (const char*)Al;
    const char* pWh = (const char*)Wh;
    const char* pWl = (const char*)Wl;
    const size_t rowb = (size_t)KDIM * 2;      // bytes per gmem row

    uint32_t smb = sm32(smem);

    // --- per-thread cp.async assignments (4 x 16B per stage) ---
    // idx in [0,1024): part(2b) | row(7b) | seg(1b); each part region = 4KB.
    auto load_stage = [&](int c, int st) {
        uint32_t sb = smb + st * 16384;
        int kb = c * 32;                       // byte offset of k16 chunk
#pragma unroll
        for (int i = 0; i < 4; i++) {
            int idx = tid + i * 256;
            int part = idx >> 8, v = idx & 255;
            int row = v >> 1, seg = v & 1;
            uint32_t off = (uint32_t)(row * 32 + seg * 16);
            uint32_t dst = sb + part * 4096 + swz(off);
            const char* src;
            size_t go;
            if (part < 2) {
                go = (size_t)(m0 + row) * rowb + kb + seg * 16;
                src = part ? pAl : pAh;
            } else {
                go = (size_t)(n0 + row) * rowb + kb + seg * 16;
                src = (part == 2) ? pWh : pWl;
            }
            cpa16(dst, src + go);
        }
    };

    // --- ldmatrix per-lane offsets (within a 4KB part region) ---
    uint32_t aoff[4], boff[2];
    {
        int arow = wm * 64 + (lane & 15);
        int akc = (lane >> 4) * 8;             // lanes 16-31 read k+8 matrices
#pragma unroll
        for (int mt = 0; mt < 4; mt++)
            aoff[mt] = swz((uint32_t)((arow + mt * 16) * 32 + akc * 2));
        int brow = wn * 32 + ((lane >> 4) << 3) + (lane & 7);
        int bkc = ((lane >> 3) & 1) * 8;
#pragma unroll
        for (int nt2 = 0; nt2 < 2; nt2++)
            boff[nt2] = swz((uint32_t)((brow + nt2 * 16) * 32 + bkc * 2));
    }

    float acc[4][4][4];
#pragma unroll
    for (int i = 0; i < 4; i++)
#pragma unroll
        for (int j = 0; j < 4; j++)
#pragma unroll
            for (int q = 0; q < 4; q++) acc[i][j][q] = 0.f;

    load_stage(0, 0); cp_commit();
    load_stage(1, 1); cp_commit();
    load_stage(2, 2); cp_commit();

#pragma unroll 1
    for (int c = 0; c < NC; c++) {
        int st = c % 3;
        if (c < NC - 2)       cp_wait<2>();
        else if (c == NC - 2) cp_wait<1>();
        else                  cp_wait<0>();
        __syncthreads();

        uint32_t sb = smb + st * 16384;
        uint32_t ah[4][4], al[4][4], wh[4][2], wl[4][2];
#pragma unroll
        for (int mt = 0; mt < 4; mt++) {
            ldmx4(ah[mt], sb + aoff[mt]);
            ldmx4(al[mt], sb + 4096 + aoff[mt]);
        }
#pragma unroll
        for (int nt2 = 0; nt2 < 2; nt2++) {
            uint32_t r[4];
            ldmx4(r, sb + 8192 + boff[nt2]);
            wh[2 * nt2][0] = r[0]; wh[2 * nt2][1] = r[1];
            wh[2 * nt2 + 1][0] = r[2]; wh[2 * nt2 + 1][1] = r[3];
            ldmx4(r, sb + 12288 + boff[nt2]);
            wl[2 * nt2][0] = r[0]; wl[2 * nt2][1] = r[1];
            wl[2 * nt2 + 1][0] = r[2]; wl[2 * nt2 + 1][1] = r[3];
        }
#pragma unroll
        for (int mt = 0; mt < 4; mt++)
#pragma unroll
            for (int nt = 0; nt < 4; nt++) {
                mma16816(acc[mt][nt], ah[mt], wh[nt]);
                mma16816(acc[mt][nt], ah[mt], wl[nt]);
                mma16816(acc[mt][nt], al[mt], wh[nt]);
            }
        __syncthreads();
        if (c + 3 < NC) { load_stage(c + 3, st); cp_commit(); }
    }

    // ---- epilogue: bias, fp32 store, BN stats ----
    float bv[8];
#pragma unroll
    for (int nt = 0; nt < 4; nt++) {
        int gn = n0 + wn * 32 + nt * 8 + 2 * (lane & 3);
        bv[2 * nt] = bias[gn];
        bv[2 * nt + 1] = bias[gn + 1];
    }
    float colsum[8], colsq[8];
#pragma unroll
    for (int j = 0; j < 8; j++) { colsum[j] = 0.f; colsq[j] = 0.f; }

#pragma unroll
    for (int mt = 0; mt < 4; mt++) {
        int gm = m0 + wm * 64 + mt * 16 + (lane >> 2);
#pragma unroll
        for (int nt = 0; nt < 4; nt++) {
            int gn = n0 + wn * 32 + nt * 8 + 2 * (lane & 3);
            float c0 = acc[mt][nt][0] + bv[2 * nt];
            float c1 = acc[mt][nt][1] + bv[2 * nt + 1];
            float c2 = acc[mt][nt][2] + bv[2 * nt];
            float c3 = acc[mt][nt][3] + bv[2 * nt + 1];
            *(float2*)(C + (size_t)gm * 256 + gn)       = make_float2(c0, c1);
            *(float2*)(C + (size_t)(gm + 8) * 256 + gn) = make_float2(c2, c3);
            colsum[2 * nt]     += c0 + c2;
            colsum[2 * nt + 1] += c1 + c3;
            colsq[2 * nt]      += c0 * c0 + c2 * c2;
            colsq[2 * nt + 1]  += c1 * c1 + c3 * c3;
        }
    }

    __syncthreads();                    // stage smem reusable now
    float* ssum = (float*)smem;         // 128 floats
    float* ssq  = ssum + 128;           // 128 floats
    ((float*)smem)[tid] = 0.f;          // zero 256 floats
    __syncthreads();
#pragma unroll
    for (int nt = 0; nt < 4; nt++) {
        int cl = wn * 32 + nt * 8 + 2 * (lane & 3);
        atomicAdd(&ssum[cl],     colsum[2 * nt]);
        atomicAdd(&ssum[cl + 1], colsum[2 * nt + 1]);
        atomicAdd(&ssq[cl],      colsq[2 * nt]);
        atomicAdd(&ssq[cl + 1],  colsq[2 * nt + 1]);
    }
    __syncthreads();
    if (tid < 128) {
        atomicAdd(&gsum[n0 + tid], ssum[tid]);
        atomicAdd(&gsq[n0 + tid],  ssq[tid]);
    }
}

__global__ void __launch_bounds__(256) gemm0_kernel(const float* __restrict__ b0) {
    gemm_body<K0_>(g_Ahi, g_Alo, g_W0hi, g_W0lo, b0, g_y0, g_sum0, g_sq0);
}
__global__ void __launch_bounds__(256) gemm1k_kernel(const float* __restrict__ b1) {
    gemm_body<M0_>(g_Zhi, g_Zlo, g_W1hi, g_W1lo, b1, g_y1, g_sum1, g_sq1);
}

// ---------------- kernel: finalize BN stats -> scale/shift ------------------
__global__ void finalize0_kernel(const float* __restrict__ gamma,
                                 const float* __restrict__ beta) {
    int c = threadIdx.x;
    float cnt = (float)MTOT;
    float mean = g_sum0[c] / cnt;
    float var = g_sq0[c] / cnt - mean * mean;
    float inv = rsqrtf(var + 1e-5f);
    float sc = gamma[c] * inv;
    g_scale0[c] = sc;
    g_shift0[c] = beta[c] - mean * sc;
}
__global__ void finalize1_kernel(const float* __restrict__ gamma,
                                 const float* __restrict__ beta) {
    int c = threadIdx.x;
    float cnt = (float)MTOT;
    float mean = g_sum1[c] / cnt;
    float var = g_sq1[c] / cnt - mean * mean;
    float inv = rsqrtf(var + 1e-5f);
    float sc = gamma[c] * inv;
    g_scale1[c] = sc;
    g_shift1[c] = beta[c] - mean * sc;
}

// ---------------- kernel: BN + ReLU on y0 -> bf16 hi/lo Z -------------------
__global__ void bnrelu0_kernel() {
    size_t i4 = (size_t)blockIdx.x * 256 + threadIdx.x;   // float4 index
    float4 v = ((const float4*)g_y0)[i4];
    int c = ((int)(i4 & 63)) * 4;                          // 64 float4 per 256-ch row
    float x0 = fmaxf(v.x * g_scale0[c + 0] + g_shift0[c + 0], 0.f);
    float x1 = fmaxf(v.y * g_scale0[c + 1] + g_shift0[c + 1], 0.f);
    float x2 = fmaxf(v.z * g_scale0[c + 2] + g_shift0[c + 2], 0.f);
    float x3 = fmaxf(v.w * g_scale0[c + 3] + g_shift0[c + 3], 0.f);
    float h0, l0, h1, l1, h2, l2, h3, l3;
    split_bf(x0, h0, l0); split_bf(x1, h1, l1);
    split_bf(x2, h2, l2); split_bf(x3, h3, l3);
    ((uint2*)g_Zhi)[i4] = make_uint2(packbf(h0, h1), packbf(h2, h3));
    ((uint2*)g_Zlo)[i4] = make_uint2(packbf(l0, l1), packbf(l2, l3));
}

// ---------------- kernel: BN + ReLU + transpose -> out [B, M1, N] -----------
__global__ void bnrelu1_transpose_kernel(float* __restrict__ out) {
    __shared__ float tile[32][33];
    int b = blockIdx.z;
    int n0 = blockIdx.x * 32, o0 = blockIdx.y * 32;
    int tx = threadIdx.x, ty = threadIdx.y;
    float sc = g_scale1[o0 + tx];
    float sh = g_shift1[o0 + tx];
    const float* ip = g_y1 + (size_t)b * N_ * M1_;
#pragma unroll
    for (int i = 0; i < 4; i++) {
        int r = ty + i * 8;
        float v = ip[(size_t)(n0 + r) * M1_ + o0 + tx];
        tile[r][tx] = fmaxf(v * sc + sh, 0.f);
    }
    __syncthreads();
    float* op = out + (size_t)b * M1_ * N_;
#pragma unroll
    for (int i = 0; i < 4; i++) {
        int r = ty + i * 8;
        op[(size_t)(o0 + r) * N_ + n0 + tx] = tile[tx][r];
    }
}

// ---------------- launch ----------------------------------------------------
extern "C" void kernel_launch(void* const* d_in, const int* in_sizes, int n_in,
                              void* d_out, int out_size) {
    const float* xyz1 = (const float*)d_in[0];
    const float* xyz2 = (const float*)d_in[1];
    const float* p1   = (const float*)d_in[2];
    const float* p2   = (const float*)d_in[3];
    const float* w0   = (const float*)d_in[4];
    const float* b0   = (const float*)d_in[5];
    const float* g0   = (const float*)d_in[6];
    const float* be0  = (const float*)d_in[7];
    const float* w1   = (const float*)d_in[8];
    const float* b1   = (const float*)d_in[9];
    const float* g1   = (const float*)d_in[10];
    const float* be1  = (const float*)d_in[11];
    float* out = (float*)d_out;

    zero_stats_kernel<<<1, 256>>>();
    convw0_kernel<<<(M0_ * K0_ + 255) / 256, 256>>>(w0);
    convw1_kernel<<<(M1_ * M0_ + 255) / 256, 256>>>(w1);
    transpose_p1_kernel<<<dim3(N_ / 32, C1_ / 32, B_), dim3(32, 8)>>>(p1);
    transpose_p2_kernel<<<dim3(S_ / 32, C2_ / 32, B_), dim3(32, 8)>>>(p2);
    knn_kernel<<<dim3(N_ / 128, B_), 128>>>(xyz1, xyz2);
    gather_kernel<<<dim3(N_ / 8, B_), 256>>>();

    gemm0_kernel<<<dim3(MTOT / 128, M0_ / 128), 256>>>(b0);
    finalize0_kernel<<<1, 256>>>(g0, be0);
    bnrelu0_kernel<<<(unsigned)((size_t)MTOT * M0_ / 4 / 256), 256>>>();

    gemm1k_kernel<<<dim3(MTOT / 128, M1_ / 128), 256>>>(b1);
    finalize1_kernel<<<1, 256>>>(g1, be1);
    bnrelu1_transpose_kernel<<<dim3(N_ / 32, M1_ / 32, B_), dim3(32, 8)>>>(out);
}

// round 13
// speedup vs baseline: 1.8976x; 1.1810x over previous
#include <cuda_runtime.h>
#include <cuda_fp16.h>
#include <cstdint>
#include <cstddef>

// Problem dims (fixed by the dataset)
#define B_   16
#define N_   4096
#define S_   1024
#define C1_  256
#define C2_  256
#define K0_  512      // C1+C2
#define M0_  256
#define M1_  256
#define MTOT (B_*N_)  // 65536 rows (b*N+n)

// ---------------- scratch (static device globals; no cudaMalloc allowed) ----
__device__ __align__(16) __half g_A[(size_t)MTOT * K0_];    // 64 MB concat activations fp16
__device__ __align__(16) __half g_Z[(size_t)MTOT * M0_];    // 32 MB layer-1 input fp16
__device__ __align__(16) __half g_W0h[(size_t)M0_ * K0_], g_W0l[(size_t)M0_ * K0_];
__device__ __align__(16) __half g_W1h[(size_t)M1_ * M0_], g_W1l[(size_t)M1_ * M0_];
__device__ float g_p2t[(size_t)B_ * S_ * C2_];    // [B, S, C2]  transposed points2
__device__ int   g_idx[(size_t)B_ * N_ * 3];
__device__ float g_w[(size_t)B_ * N_ * 3];
__device__ float g_y0[(size_t)MTOT * M0_];        // layer-0 pre-BN fp32
__device__ float g_y1[(size_t)MTOT * M1_];        // layer-1 pre-BN fp32
__device__ float g_sum0[M0_], g_sq0[M0_], g_sum1[M1_], g_sq1[M1_];
__device__ float g_scale0[M0_], g_shift0[M0_], g_scale1[M1_], g_shift1[M1_];

// ---------------- small helpers ---------------------------------------------
static __device__ __forceinline__ uint32_t sm32(const void* p) {
    return (uint32_t)__cvta_generic_to_shared(p);
}
static __device__ __forceinline__ uint32_t packh(float a, float b) {
    __half2 t = __floats2half2_rn(a, b);
    return *reinterpret_cast<uint32_t*>(&t);
}
static __device__ __forceinline__ void cpa16(uint32_t dst, const void* src) {
    asm volatile("cp.async.cg.shared.global [%0], [%1], 16;" :: "r"(dst), "l"(src));
}
static __device__ __forceinline__ void cp_commit() {
    asm volatile("cp.async.commit_group;" ::: "memory");
}
template <int n>
static __device__ __forceinline__ void cp_wait() {
    asm volatile("cp.async.wait_group %0;" :: "n"(n) : "memory");
}
// ldmatrix x4 (b16, non-transposed)
static __device__ __forceinline__ void ldmx4(uint32_t r[4], uint32_t addr) {
    asm volatile("ldmatrix.sync.aligned.m8n8.x4.shared.b16 {%0,%1,%2,%3}, [%4];"
                 : "=r"(r[0]), "=r"(r[1]), "=r"(r[2]), "=r"(r[3]) : "r"(addr));
}
// HMMA m16n8k16 fp16 -> f32 accumulate (base sm_80+ PTX, legal on compute_103)
static __device__ __forceinline__ void mma16816(float c[4], const uint32_t a[4],
                                                const uint32_t b[2]) {
    asm volatile(
        "mma.sync.aligned.m16n8k16.row.col.f32.f16.f16.f32 "
        "{%0,%1,%2,%3}, {%4,%5,%6,%7}, {%8,%9}, {%0,%1,%2,%3};"
        : "+f"(c[0]), "+f"(c[1]), "+f"(c[2]), "+f"(c[3])
        : "r"(a[0]), "r"(a[1]), "r"(a[2]), "r"(a[3]), "r"(b[0]), "r"(b[1]));
}
// swizzle for 32B rows (8-row atom spans 256B): XOR bit4 with bit7
static __device__ __forceinline__ uint32_t swz(uint32_t off) {
    return off ^ ((off >> 3) & 0x10);
}

// ---------------- kernel: zero BN-stat accumulators -------------------------
__global__ void zero_stats_kernel() {
    int t = threadIdx.x;          // 256 threads
    g_sum0[t] = 0.f; g_sq0[t] = 0.f;
    g_sum1[t] = 0.f; g_sq1[t] = 0.f;
}

// ---------------- kernels: fp32 weights -> fp16 hi/lo (globals in dev code) -
__global__ void convw0_kernel(const float* __restrict__ w) {
    int i = blockIdx.x * 256 + threadIdx.x;
    if (i < M0_ * K0_) {
        float v = w[i];
        __half h = __float2half_rn(v);
        g_W0h[i] = h;
        g_W0l[i] = __float2half_rn(v - __half2float(h));
    }
}
__global__ void convw1_kernel(const float* __restrict__ w) {
    int i = blockIdx.x * 256 + threadIdx.x;
    if (i < M1_ * M0_) {
        float v = w[i];
        __half h = __float2half_rn(v);
        g_W1h[i] = h;
        g_W1l[i] = __float2half_rn(v - __half2float(h));
    }
}

// ---------------- kernel: transpose points1 [B,C1,N] -> g_A[:, 0:256] -------
__global__ void transpose_p1_kernel(const float* __restrict__ p1) {
    __shared__ float tile[32][33];
    int b = blockIdx.z;
    int n0 = blockIdx.x * 32, c0 = blockIdx.y * 32;
    int tx = threadIdx.x, ty = threadIdx.y;
    const float* ip = p1 + (size_t)b * C1_ * N_;
#pragma unroll
    for (int i = 0; i < 4; i++) {
        int r = ty + i * 8;
        tile[r][tx] = ip[(size_t)(c0 + r) * N_ + n0 + tx];
    }
    __syncthreads();
    size_t rb = (size_t)b * N_ * K0_;
#pragma unroll
    for (int i = 0; i < 4; i++) {
        int r = ty + i * 8;
        g_A[rb + (size_t)(n0 + r) * K0_ + c0 + tx] = __float2half_rn(tile[tx][r]);
    }
}

// ---------------- kernel: transpose points2 [B,C2,S] -> p2t [B,S,C2] --------
__global__ void transpose_p2_kernel(const float* __restrict__ p2) {
    __shared__ float tile[32][33];
    int b = blockIdx.z;
    int s0 = blockIdx.x * 32, c0 = blockIdx.y * 32;
    int tx = threadIdx.x, ty = threadIdx.y;
    const float* ip = p2 + (size_t)b * C2_ * S_;
    float* op = g_p2t + (size_t)b * S_ * C2_;
#pragma unroll
    for (int i = 0; i < 4; i++) {
        int r = ty + i * 8;
        tile[r][tx] = ip[(size_t)(c0 + r) * S_ + s0 + tx];
    }
    __syncthreads();
#pragma unroll
    for (int i = 0; i < 4; i++) {
        int r = ty + i * 8;
        op[(size_t)(s0 + r) * C2_ + c0 + tx] = tile[tx][r];
    }
}

// ---------------- kernel: 3-NN, 4 independent chains for ILP ----------------
__global__ void knn_kernel(const float* __restrict__ xyz1,
                           const float* __restrict__ xyz2) {
    __shared__ float4 s4[S_];
    int b = blockIdx.y;
    const float* x2 = xyz2 + (size_t)b * 3 * S_;
    for (int j = threadIdx.x; j < S_; j += 128) {
        float a = x2[j], c = x2[S_ + j], d = x2[2 * S_ + j];
        s4[j] = make_float4(a, c, d, a * a + c * c + d * d);
    }
    __syncthreads();

    int n = blockIdx.x * 128 + threadIdx.x;
    const float* x1 = xyz1 + (size_t)b * 3 * N_;
    float px = x1[n], py = x1[N_ + n], pz = x1[2 * N_ + n];
    float n1 = px * px + py * py + pz * pz;

    float cd0[4], cd1[4], cd2[4];
    int   ci0[4], ci1[4], ci2[4];
#pragma unroll
    for (int c = 0; c < 4; c++) {
        cd0[c] = cd1[c] = cd2[c] = 1e30f;
        ci0[c] = ci1[c] = ci2[c] = 0;
    }
    for (int t = 0; t < 256; t++) {
#pragma unroll
        for (int c = 0; c < 4; c++) {
            int s = t + c * 256;
            float4 w = s4[s];
            float dot = px * w.x + py * w.y + pz * w.z;
            float d = n1 + w.w - 2.f * dot;
            if (d < cd2[c]) {
                if (d < cd1[c]) {
                    cd2[c] = cd1[c]; ci2[c] = ci1[c];
                    if (d < cd0[c]) { cd1[c] = cd0[c]; ci1[c] = ci0[c]; cd0[c] = d; ci0[c] = s; }
                    else            { cd1[c] = d;      ci1[c] = s; }
                } else { cd2[c] = d; ci2[c] = s; }
            }
        }
    }
    // merge 12 candidates
    float d0 = 1e30f, d1 = 1e30f, d2 = 1e30f;
    int i0 = 0, i1 = 0, i2 = 0;
    auto ins = [&](float d, int i) {
        if (d < d2) {
            if (d < d1) {
                d2 = d1; i2 = i1;
                if (d < d0) { d1 = d0; i1 = i0; d0 = d; i0 = i; }
                else        { d1 = d;  i1 = i; }
            } else { d2 = d; i2 = i; }
        }
    };
#pragma unroll
    for (int c = 0; c < 4; c++) { ins(cd0[c], ci0[c]); ins(cd1[c], ci1[c]); ins(cd2[c], ci2[c]); }

    float r0 = 1.f / (d0 + 1e-8f);
    float r1 = 1.f / (d1 + 1e-8f);
    float r2 = 1.f / (d2 + 1e-8f);
    float rs = r0 + r1 + r2;
    size_t base = ((size_t)b * N_ + n) * 3;
    g_idx[base] = i0; g_idx[base + 1] = i1; g_idx[base + 2] = i2;
    g_w[base] = r0 / rs; g_w[base + 1] = r1 / rs; g_w[base + 2] = r2 / rs;
}

// ---------------- kernel: weighted gather -> g_A[:, 256:512] ----------------
__global__ void gather_kernel() {
    int b = blockIdx.y;
    int warp = threadIdx.x >> 5, lane = threadIdx.x & 31;
    int n = blockIdx.x * 8 + warp;
    size_t base = ((size_t)b * N_ + n) * 3;
    int i0 = g_idx[base], i1 = g_idx[base + 1], i2 = g_idx[base + 2];
    float w0 = g_w[base], w1 = g_w[base + 1], w2 = g_w[base + 2];
    const float4* r0 = (const float4*)(g_p2t + ((size_t)b * S_ + i0) * C2_);
    const float4* r1 = (const float4*)(g_p2t + ((size_t)b * S_ + i1) * C2_);
    const float4* r2 = (const float4*)(g_p2t + ((size_t)b * S_ + i2) * C2_);
    size_t rowe = ((size_t)b * N_ + n) * K0_ + C1_;
#pragma unroll
    for (int t = 0; t < 2; t++) {
        int c = lane + t * 32;                 // 64 float4 per 256-ch half
        float4 a = r0[c], bb = r1[c], cc = r2[c];
        float ox = w0 * a.x + w1 * bb.x + w2 * cc.x;
        float oy = w0 * a.y + w1 * bb.y + w2 * cc.y;
        float oz = w0 * a.z + w1 * bb.z + w2 * cc.z;
        float ow = w0 * a.w + w1 * bb.w + w2 * cc.w;
        *reinterpret_cast<uint2*>(g_A + rowe + 4 * c) =
            make_uint2(packh(ox, oy), packh(oz, ow));
    }
}

// ---------------- HMMA 2-term fp16 GEMM: C = A[M,K]*W[256,K]^T + bias -------
// W = Wh + Wl (fp16 split, exact to ~22 bits); A single fp16.
// CTA tile 128x128, 8 warps (2x4), warp tile 64x32, BK=16, 3-stage cp.async.
// Accumulates per-output-channel sum/sumsq (BN training stats).
template <int KDIM>
static __device__ __forceinline__ void gemm_body(
    const __half* __restrict__ A,
    const __half* __restrict__ Wh, const __half* __restrict__ Wl,
    const float* __restrict__ bias, float* __restrict__ C,
    float* __restrict__ gsum, float* __restrict__ gsq) {
    constexpr int NC = KDIM / 16;              // 32 or 16 k-steps
    __shared__ __align__(1024) char smem[3 * 12288];   // 3 stages x (A|Wh|Wl 4KB each)

    int tid = threadIdx.x, lane = tid & 31, wid = tid >> 5;
    int wm = wid & 1, wn = wid >> 1;           // 2 x 4 warp grid
    int m0 = blockIdx.x * 128, n0 = blockIdx.y * 128;

    const char* pA  = (const char*)A;
    const char* pWh = (const char*)Wh;
    const char* pWl = (const char*)Wl;
    const size_t rowb = (size_t)KDIM * 2;      // bytes per gmem row

    uint32_t smb = sm32(smem);

    // --- per-thread cp.async assignments (3 x 16B per stage) ---
    // idx in [0,768): part | row(7b) | seg(1b); each part region = 4KB.
    auto load_stage = [&](int c, int st) {
        uint32_t sb = smb + st * 12288;
        int kb = c * 32;                       // byte offset of k16 chunk
#pragma unroll
        for (int i = 0; i < 3; i++) {
            int idx = tid + i * 256;
            int part = idx >> 8, v = idx & 255;
            int row = v >> 1, seg = v & 1;
            uint32_t off = (uint32_t)(row * 32 + seg * 16);
            uint32_t dst = sb + part * 4096 + swz(off);
            const char* src;
            size_t go;
            if (part == 0) {
                go = (size_t)(m0 + row) * rowb + kb + seg * 16;
                src = pA;
            } else {
                go = (size_t)(n0 + row) * rowb + kb + seg * 16;
                src = (part == 1) ? pWh : pWl;
            }
            cpa16(dst, src + go);
        }
    };

    // --- ldmatrix per-lane offsets (within a 4KB part region) ---
    uint32_t aoff[4], boff[2];
    {
        int arow = wm * 64 + (lane & 15);
        int akc = (lane >> 4) * 8;             // lanes 16-31 read k+8 matrices
#pragma unroll
        for (int mt = 0; mt < 4; mt++)
            aoff[mt] = swz((uint32_t)((arow + mt * 16) * 32 + akc * 2));
        int brow = wn * 32 + ((lane >> 4) << 3) + (lane & 7);
        int bkc = ((lane >> 3) & 1) * 8;
#pragma unroll
        for (int nt2 = 0; nt2 < 2; nt2++)
            boff[nt2] = swz((uint32_t)((brow + nt2 * 16) * 32 + bkc * 2));
    }

    float acc[4][4][4];
#pragma unroll
    for (int i = 0; i < 4; i++)
#pragma unroll
        for (int j = 0; j < 4; j++)
#pragma unroll
            for (int q = 0; q < 4; q++) acc[i][j][q] = 0.f;

    load_stage(0, 0); cp_commit();
    load_stage(1, 1); cp_commit();
    load_stage(2, 2); cp_commit();

#pragma unroll 1
    for (int c = 0; c < NC; c++) {
        int st = c % 3;
        if (c < NC - 2)       cp_wait<2>();
        else if (c == NC - 2) cp_wait<1>();
        else                  cp_wait<0>();
        __syncthreads();

        uint32_t sb = smb + st * 12288;
        uint32_t ah[4][4], wh[4][2], wl[4][2];
#pragma unroll
        for (int mt = 0; mt < 4; mt++) ldmx4(ah[mt], sb + aoff[mt]);
#pragma unroll
        for (int nt2 = 0; nt2 < 2; nt2++) {
            uint32_t r[4];
            ldmx4(r, sb + 4096 + boff[nt2]);
            wh[2 * nt2][0] = r[0]; wh[2 * nt2][1] = r[1];
            wh[2 * nt2 + 1][0] = r[2]; wh[2 * nt2 + 1][1] = r[3];
            ldmx4(r, sb + 8192 + boff[nt2]);
            wl[2 * nt2][0] = r[0]; wl[2 * nt2][1] = r[1];
            wl[2 * nt2 + 1][0] = r[2]; wl[2 * nt2 + 1][1] = r[3];
        }
#pragma unroll
        for (int mt = 0; mt < 4; mt++)
#pragma unroll
            for (int nt = 0; nt < 4; nt++) {
                mma16816(acc[mt][nt], ah[mt], wh[nt]);
                mma16816(acc[mt][nt], ah[mt], wl[nt]);
            }
        __syncthreads();
        if (c + 3 < NC) { load_stage(c + 3, st); cp_commit(); }
    }

    // ---- epilogue: bias, fp32 store, BN stats ----
    float bv[8];
#pragma unroll
    for (int nt = 0; nt < 4; nt++) {
        int gn = n0 + wn * 32 + nt * 8 + 2 * (lane & 3);
        bv[2 * nt] = bias[gn];
        bv[2 * nt + 1] = bias[gn + 1];
    }
    float colsum[8], colsq[8];
#pragma unroll
    for (int j = 0; j < 8; j++) { colsum[j] = 0.f; colsq[j] = 0.f; }

#pragma unroll
    for (int mt = 0; mt < 4; mt++) {
        int gm = m0 + wm * 64 + mt * 16 + (lane >> 2);
#pragma unroll
        for (int nt = 0; nt < 4; nt++) {
            int gn = n0 + wn * 32 + nt * 8 + 2 * (lane & 3);
            float c0 = acc[mt][nt][0] + bv[2 * nt];
            float c1 = acc[mt][nt][1] + bv[2 * nt + 1];
            float c2 = acc[mt][nt][2] + bv[2 * nt];
            float c3 = acc[mt][nt][3] + bv[2 * nt + 1];
            *(float2*)(C + (size_t)gm * 256 + gn)       = make_float2(c0, c1);
            *(float2*)(C + (size_t)(gm + 8) * 256 + gn) = make_float2(c2, c3);
            colsum[2 * nt]     += c0 + c2;
            colsum[2 * nt + 1] += c1 + c3;
            colsq[2 * nt]      += c0 * c0 + c2 * c2;
            colsq[2 * nt + 1]  += c1 * c1 + c3 * c3;
        }
    }

    __syncthreads();                    // stage smem reusable now
    float* ssum = (float*)smem;         // 128 floats
    float* ssq  = ssum + 128;           // 128 floats
    ((float*)smem)[tid] = 0.f;          // zero 256 floats
    __syncthreads();
#pragma unroll
    for (int nt = 0; nt < 4; nt++) {
        int cl = wn * 32 + nt * 8 + 2 * (lane & 3);
        atomicAdd(&ssum[cl],     colsum[2 * nt]);
        atomicAdd(&ssum[cl + 1], colsum[2 * nt + 1]);
        atomicAdd(&ssq[cl],      colsq[2 * nt]);
        atomicAdd(&ssq[cl + 1],  colsq[2 * nt + 1]);
    }
    __syncthreads();
    if (tid < 128) {
        atomicAdd(&gsum[n0 + tid], ssum[tid]);
        atomicAdd(&gsq[n0 + tid],  ssq[tid]);
    }
}

__global__ void __launch_bounds__(256) gemm0_kernel(const float* __restrict__ b0) {
    gemm_body<K0_>(g_A, g_W0h, g_W0l, b0, g_y0, g_sum0, g_sq0);
}
__global__ void __launch_bounds__(256) gemm1k_kernel(const float* __restrict__ b1) {
    gemm_body<M0_>(g_Z, g_W1h, g_W1l, b1, g_y1, g_sum1, g_sq1);
}

// ---------------- kernel: finalize BN stats -> scale/shift ------------------
__global__ void finalize0_kernel(const float* __restrict__ gamma,
                                 const float* __restrict__ beta) {
    int c = threadIdx.x;
    float cnt = (float)MTOT;
    float mean = g_sum0[c] / cnt;
    float var = g_sq0[c] / cnt - mean * mean;
    float inv = rsqrtf(var + 1e-5f);
    float sc = gamma[c] * inv;
    g_scale0[c] = sc;
    g_shift0[c] = beta[c] - mean * sc;
}
__global__ void finalize1_kernel(const float* __restrict__ gamma,
                                 const float* __restrict__ beta) {
    int c = threadIdx.x;
    float cnt = (float)MTOT;
    float mean = g_sum1[c] / cnt;
    float var = g_sq1[c] / cnt - mean * mean;
    float inv = rsqrtf(var + 1e-5f);
    float sc = gamma[c] * inv;
    g_scale1[c] = sc;
    g_shift1[c] = beta[c] - mean * sc;
}

// ---------------- kernel: BN + ReLU on y0 -> fp16 Z -------------------------
__global__ void bnrelu0_kernel() {
    size_t i4 = (size_t)blockIdx.x * 256 + threadIdx.x;   // float4 index
    float4 v = ((const float4*)g_y0)[i4];
    int c = ((int)(i4 & 63)) * 4;                          // 64 float4 per 256-ch row
    float x0 = fmaxf(v.x * g_scale0[c + 0] + g_shift0[c + 0], 0.f);
    float x1 = fmaxf(v.y * g_scale0[c + 1] + g_shift0[c + 1], 0.f);
    float x2 = fmaxf(v.z * g_scale0[c + 2] + g_shift0[c + 2], 0.f);
    float x3 = fmaxf(v.w * g_scale0[c + 3] + g_shift0[c + 3], 0.f);
    ((uint2*)g_Z)[i4] = make_uint2(packh(x0, x1), packh(x2, x3));
}

// ---------------- kernel: BN + ReLU + transpose -> out [B, M1, N] -----------
__global__ void bnrelu1_transpose_kernel(float* __restrict__ out) {
    __shared__ float tile[32][33];
    int b = blockIdx.z;
    int n0 = blockIdx.x * 32, o0 = blockIdx.y * 32;
    int tx = threadIdx.x, ty = threadIdx.y;
    float sc = g_scale1[o0 + tx];
    float sh = g_shift1[o0 + tx];
    const float* ip = g_y1 + (size_t)b * N_ * M1_;
#pragma unroll
    for (int i = 0; i < 4; i++) {
        int r = ty + i * 8;
        float v = ip[(size_t)(n0 + r) * M1_ + o0 + tx];
        tile[r][tx] = fmaxf(v * sc + sh, 0.f);
    }
    __syncthreads();
    float* op = out + (size_t)b * M1_ * N_;
#pragma unroll
    for (int i = 0; i < 4; i++) {
        int r = ty + i * 8;
        op[(size_t)(o0 + r) * N_ + n0 + tx] = tile[tx][r];
    }
}

// ---------------- launch ----------------------------------------------------
extern "C" void kernel_launch(void* const* d_in, const int* in_sizes, int n_in,
                              void* d_out, int out_size) {
    const float* xyz1 = (const float*)d_in[0];
    const float* xyz2 = (const float*)d_in[1];
    const float* p1   = (const float*)d_in[2];
    const float* p2   = (const float*)d_in[3];
    const float* w0   = (const float*)d_in[4];
    const float* b0   = (const float*)d_in[5];
    const float* g0   = (const float*)d_in[6];
    const float* be0  = (const float*)d_in[7];
    const float* w1   = (const float*)d_in[8];
    const float* b1   = (const float*)d_in[9];
    const float* g1   = (const float*)d_in[10];
    const float* be1  = (const float*)d_in[11];
    float* out = (float*)d_out;

    zero_stats_kernel<<<1, 256>>>();
    convw0_kernel<<<(M0_ * K0_ + 255) / 256, 256>>>(w0);
    convw1_kernel<<<(M1_ * M0_ + 255) / 256, 256>>>(w1);
    transpose_p1_kernel<<<dim3(N_ / 32, C1_ / 32, B_), dim3(32, 8)>>>(p1);
    transpose_p2_kernel<<<dim3(S_ / 32, C2_ / 32, B_), dim3(32, 8)>>>(p2);
    knn_kernel<<<dim3(N_ / 128, B_), 128>>>(xyz1, xyz2);
    gather_kernel<<<dim3(N_ / 8, B_), 256>>>();

    gemm0_kernel<<<dim3(MTOT / 128, M0_ / 128), 256>>>(b0);
    finalize0_kernel<<<1, 256>>>(g0, be0);
    bnrelu0_kernel<<<(unsigned)((size_t)MTOT * M0_ / 4 / 256), 256>>>();

    gemm1k_kernel<<<dim3(MTOT / 128, M1_ / 128), 256>>>(b1);
    finalize1_kernel<<<1, 256>>>(g1, be1);
    bnrelu1_transpose_kernel<<<dim3(N_ / 32, M1_ / 32, B_), dim3(32, 8)>>>(out);
}

// round 14
// speedup vs baseline: 2.2565x; 1.1892x over previous
#include <cuda_runtime.h>
#include <cuda_fp16.h>
#include <cstdint>
#include <cstddef>

// Problem dims (fixed by the dataset)
#define B_   16
#define N_   4096
#define S_   1024
#define C1_  256
#define C2_  256
#define K0_  512      // C1+C2
#define M0_  256
#define M1_  256
#define MTOT (B_*N_)  // 65536 rows (b*N+n)

// ---------------- scratch (static device globals; no cudaMalloc allowed) ----
__device__ __align__(16) __half g_A[(size_t)MTOT * K0_];    // 64 MB concat activations fp16
__device__ __align__(16) __half g_Z[(size_t)MTOT * M0_];    // 32 MB layer-1 input fp16
__device__ __align__(16) __half g_W0h[(size_t)M0_ * K0_];
__device__ __align__(16) __half g_W1h[(size_t)M1_ * M0_];
__device__ float g_p2t[(size_t)B_ * S_ * C2_];    // [B, S, C2]  transposed points2
__device__ int   g_idx[(size_t)B_ * N_ * 3];
__device__ float g_w[(size_t)B_ * N_ * 3];
__device__ float g_y0[(size_t)MTOT * M0_];        // layer-0 pre-BN fp32
__device__ float g_y1[(size_t)MTOT * M1_];        // layer-1 pre-BN fp32
__device__ float g_sum0[M0_], g_sq0[M0_], g_sum1[M1_], g_sq1[M1_];
__device__ float g_scale0[M0_], g_shift0[M0_], g_scale1[M1_], g_shift1[M1_];

// ---------------- small helpers ---------------------------------------------
static __device__ __forceinline__ uint32_t sm32(const void* p) {
    return (uint32_t)__cvta_generic_to_shared(p);
}
static __device__ __forceinline__ uint32_t packh(float a, float b) {
    __half2 t = __floats2half2_rn(a, b);
    return *reinterpret_cast<uint32_t*>(&t);
}
static __device__ __forceinline__ void cpa16(uint32_t dst, const void* src) {
    asm volatile("cp.async.cg.shared.global [%0], [%1], 16;" :: "r"(dst), "l"(src));
}
static __device__ __forceinline__ void cp_commit() {
    asm volatile("cp.async.commit_group;" ::: "memory");
}
template <int n>
static __device__ __forceinline__ void cp_wait() {
    asm volatile("cp.async.wait_group %0;" :: "n"(n) : "memory");
}
// ldmatrix x4 (b16, non-transposed)
static __device__ __forceinline__ void ldmx4(uint32_t r[4], uint32_t addr) {
    asm volatile("ldmatrix.sync.aligned.m8n8.x4.shared.b16 {%0,%1,%2,%3}, [%4];"
                 : "=r"(r[0]), "=r"(r[1]), "=r"(r[2]), "=r"(r[3]) : "r"(addr));
}
// HMMA m16n8k16 fp16 -> f32 accumulate (base sm_80+ PTX, legal on compute_103)
static __device__ __forceinline__ void mma16816(float c[4], const uint32_t a[4],
                                                const uint32_t b[2]) {
    asm volatile(
        "mma.sync.aligned.m16n8k16.row.col.f32.f16.f16.f32 "
        "{%0,%1,%2,%3}, {%4,%5,%6,%7}, {%8,%9}, {%0,%1,%2,%3};"
        : "+f"(c[0]), "+f"(c[1]), "+f"(c[2]), "+f"(c[3])
        : "r"(a[0]), "r"(a[1]), "r"(a[2]), "r"(a[3]), "r"(b[0]), "r"(b[1]));
}
// swizzle for 32B rows (8-row atom spans 256B): XOR bit4 with bit7
static __device__ __forceinline__ uint32_t swz(uint32_t off) {
    return off ^ ((off >> 3) & 0x10);
}

// ---------------- kernel: zero BN-stat accumulators -------------------------
__global__ void zero_stats_kernel() {
    int t = threadIdx.x;          // 256 threads
    g_sum0[t] = 0.f; g_sq0[t] = 0.f;
    g_sum1[t] = 0.f; g_sq1[t] = 0.f;
}

// ---------------- kernels: fp32 weights -> fp16 (globals in dev code) -------
__global__ void convw0_kernel(const float* __restrict__ w) {
    int i = blockIdx.x * 256 + threadIdx.x;
    if (i < M0_ * K0_) g_W0h[i] = __float2half_rn(w[i]);
}
__global__ void convw1_kernel(const float* __restrict__ w) {
    int i = blockIdx.x * 256 + threadIdx.x;
    if (i < M1_ * M0_) g_W1h[i] = __float2half_rn(w[i]);
}

// ---------------- kernel: transpose points1 [B,C1,N] -> g_A[:, 0:256] -------
__global__ void transpose_p1_kernel(const float* __restrict__ p1) {
    __shared__ float tile[32][33];
    int b = blockIdx.z;
    int n0 = blockIdx.x * 32, c0 = blockIdx.y * 32;
    int tx = threadIdx.x, ty = threadIdx.y;
    const float* ip = p1 + (size_t)b * C1_ * N_;
#pragma unroll
    for (int i = 0; i < 4; i++) {
        int r = ty + i * 8;
        tile[r][tx] = ip[(size_t)(c0 + r) * N_ + n0 + tx];
    }
    __syncthreads();
    size_t rb = (size_t)b * N_ * K0_;
#pragma unroll
    for (int i = 0; i < 4; i++) {
        int r = ty + i * 8;
        g_A[rb + (size_t)(n0 + r) * K0_ + c0 + tx] = __float2half_rn(tile[tx][r]);
    }
}

// ---------------- kernel: transpose points2 [B,C2,S] -> p2t [B,S,C2] --------
__global__ void transpose_p2_kernel(const float* __restrict__ p2) {
    __shared__ float tile[32][33];
    int b = blockIdx.z;
    int s0 = blockIdx.x * 32, c0 = blockIdx.y * 32;
    int tx = threadIdx.x, ty = threadIdx.y;
    const float* ip = p2 + (size_t)b * C2_ * S_;
    float* op = g_p2t + (size_t)b * S_ * C2_;
#pragma unroll
    for (int i = 0; i < 4; i++) {
        int r = ty + i * 8;
        tile[r][tx] = ip[(size_t)(c0 + r) * S_ + s0 + tx];
    }
    __syncthreads();
#pragma unroll
    for (int i = 0; i < 4; i++) {
        int r = ty + i * 8;
        op[(size_t)(s0 + r) * C2_ + c0 + tx] = tile[tx][r];
    }
}

// ---------------- kernel: 3-NN, 4 independent chains for ILP ----------------
__global__ void knn_kernel(const float* __restrict__ xyz1,
                           const float* __restrict__ xyz2) {
    __shared__ float4 s4[S_];
    int b = blockIdx.y;
    const float* x2 = xyz2 + (size_t)b * 3 * S_;
    for (int j = threadIdx.x; j < S_; j += 128) {
        float a = x2[j], c = x2[S_ + j], d = x2[2 * S_ + j];
        s4[j] = make_float4(a, c, d, a * a + c * c + d * d);
    }
    __syncthreads();

    int n = blockIdx.x * 128 + threadIdx.x;
    const float* x1 = xyz1 + (size_t)b * 3 * N_;
    float px = x1[n], py = x1[N_ + n], pz = x1[2 * N_ + n];
    float n1 = px * px + py * py + pz * pz;

    float cd0[4], cd1[4], cd2[4];
    int   ci0[4], ci1[4], ci2[4];
#pragma unroll
    for (int c = 0; c < 4; c++) {
        cd0[c] = cd1[c] = cd2[c] = 1e30f;
        ci0[c] = ci1[c] = ci2[c] = 0;
    }
    for (int t = 0; t < 256; t++) {
#pragma unroll
        for (int c = 0; c < 4; c++) {
            int s = t + c * 256;
            float4 w = s4[s];
            float dot = px * w.x + py * w.y + pz * w.z;
            float d = n1 + w.w - 2.f * dot;
            if (d < cd2[c]) {
                if (d < cd1[c]) {
                    cd2[c] = cd1[c]; ci2[c] = ci1[c];
                    if (d < cd0[c]) { cd1[c] = cd0[c]; ci1[c] = ci0[c]; cd0[c] = d; ci0[c] = s; }
                    else            { cd1[c] = d;      ci1[c] = s; }
                } else { cd2[c] = d; ci2[c] = s; }
            }
        }
    }
    // merge 12 candidates
    float d0 = 1e30f, d1 = 1e30f, d2 = 1e30f;
    int i0 = 0, i1 = 0, i2 = 0;
    auto ins = [&](float d, int i) {
        if (d < d2) {
            if (d < d1) {
                d2 = d1; i2 = i1;
                if (d < d0) { d1 = d0; i1 = i0; d0 = d; i0 = i; }
                else        { d1 = d;  i1 = i; }
            } else { d2 = d; i2 = i; }
        }
    };
#pragma unroll
    for (int c = 0; c < 4; c++) { ins(cd0[c], ci0[c]); ins(cd1[c], ci1[c]); ins(cd2[c], ci2[c]); }

    float r0 = 1.f / (d0 + 1e-8f);
    float r1 = 1.f / (d1 + 1e-8f);
    float r2 = 1.f / (d2 + 1e-8f);
    float rs = r0 + r1 + r2;
    size_t base = ((size_t)b * N_ + n) * 3;
    g_idx[base] = i0; g_idx[base + 1] = i1; g_idx[base + 2] = i2;
    g_w[base] = r0 / rs; g_w[base + 1] = r1 / rs; g_w[base + 2] = r2 / rs;
}

// ---------------- kernel: weighted gather -> g_A[:, 256:512] ----------------
__global__ void gather_kernel() {
    int b = blockIdx.y;
    int warp = threadIdx.x >> 5, lane = threadIdx.x & 31;
    int n = blockIdx.x * 8 + warp;
    size_t base = ((size_t)b * N_ + n) * 3;
    int i0 = g_idx[base], i1 = g_idx[base + 1], i2 = g_idx[base + 2];
    float w0 = g_w[base], w1 = g_w[base + 1], w2 = g_w[base + 2];
    const float4* r0 = (const float4*)(g_p2t + ((size_t)b * S_ + i0) * C2_);
    const float4* r1 = (const float4*)(g_p2t + ((size_t)b * S_ + i1) * C2_);
    const float4* r2 = (const float4*)(g_p2t + ((size_t)b * S_ + i2) * C2_);
    size_t rowe = ((size_t)b * N_ + n) * K0_ + C1_;
#pragma unroll
    for (int t = 0; t < 2; t++) {
        int c = lane + t * 32;                 // 64 float4 per 256-ch half
        float4 a = r0[c], bb = r1[c], cc = r2[c];
        float ox = w0 * a.x + w1 * bb.x + w2 * cc.x;
        float oy = w0 * a.y + w1 * bb.y + w2 * cc.y;
        float oz = w0 * a.z + w1 * bb.z + w2 * cc.z;
        float ow = w0 * a.w + w1 * bb.w + w2 * cc.w;
        *reinterpret_cast<uint2*>(g_A + rowe + 4 * c) =
            make_uint2(packh(ox, oy), packh(oz, ow));
    }
}

// ---------------- HMMA fp16 GEMM: C = A[M,K]*W[256,K]^T + bias --------------
// CTA tile 128x128, 8 warps (2x4), warp tile 64x32, BK=16, 3-stage cp.async.
// Accumulates per-output-channel sum/sumsq (BN training stats).
template <int KDIM>
static __device__ __forceinline__ void gemm_body(
    const __half* __restrict__ A, const __half* __restrict__ Wh,
    const float* __restrict__ bias, float* __restrict__ C,
    float* __restrict__ gsum, float* __restrict__ gsq) {
    constexpr int NC = KDIM / 16;              // 32 or 16 k-steps
    __shared__ __align__(1024) char smem[3 * 8192];    // 3 stages x (A|W 4KB each)

    int tid = threadIdx.x, lane = tid & 31, wid = tid >> 5;
    int wm = wid & 1, wn = wid >> 1;           // 2 x 4 warp grid
    int m0 = blockIdx.x * 128, n0 = blockIdx.y * 128;

    const char* pA = (const char*)A;
    const char* pW = (const char*)Wh;
    const size_t rowb = (size_t)KDIM * 2;      // bytes per gmem row

    uint32_t smb = sm32(smem);

    // --- per-thread cp.async assignments (2 x 16B per stage) ---
    // idx in [0,512): part | row(7b) | seg(1b); each part region = 4KB.
    auto load_stage = [&](int c, int st) {
        uint32_t sb = smb + st * 8192;
        int kb = c * 32;                       // byte offset of k16 chunk
#pragma unroll
        for (int i = 0; i < 2; i++) {
            int idx = tid + i * 256;
            int part = idx >> 8, v = idx & 255;
            int row = v >> 1, seg = v & 1;
            uint32_t off = (uint32_t)(row * 32 + seg * 16);
            uint32_t dst = sb + part * 4096 + swz(off);
            if (part == 0)
                cpa16(dst, pA + (size_t)(m0 + row) * rowb + kb + seg * 16);
            else
                cpa16(dst, pW + (size_t)(n0 + row) * rowb + kb + seg * 16);
        }
    };

    // --- ldmatrix per-lane offsets (within a 4KB part region) ---
    uint32_t aoff[4], boff[2];
    {
        int arow = wm * 64 + (lane & 15);
        int akc = (lane >> 4) * 8;             // lanes 16-31 read k+8 matrices
#pragma unroll
        for (int mt = 0; mt < 4; mt++)
            aoff[mt] = swz((uint32_t)((arow + mt * 16) * 32 + akc * 2));
        int brow = wn * 32 + ((lane >> 4) << 3) + (lane & 7);
        int bkc = ((lane >> 3) & 1) * 8;
#pragma unroll
        for (int nt2 = 0; nt2 < 2; nt2++)
            boff[nt2] = swz((uint32_t)((brow + nt2 * 16) * 32 + bkc * 2));
    }

    float acc[4][4][4];
#pragma unroll
    for (int i = 0; i < 4; i++)
#pragma unroll
        for (int j = 0; j < 4; j++)
#pragma unroll
            for (int q = 0; q < 4; q++) acc[i][j][q] = 0.f;

    load_stage(0, 0); cp_commit();
    load_stage(1, 1); cp_commit();
    load_stage(2, 2); cp_commit();

#pragma unroll 1
    for (int c = 0; c < NC; c++) {
        int st = c % 3;
        if (c < NC - 2)       cp_wait<2>();
        else if (c == NC - 2) cp_wait<1>();
        else                  cp_wait<0>();
        __syncthreads();

        uint32_t sb = smb + st * 8192;
        uint32_t ah[4][4], wh[4][2];
#pragma unroll
        for (int mt = 0; mt < 4; mt++) ldmx4(ah[mt], sb + aoff[mt]);
#pragma unroll
        for (int nt2 = 0; nt2 < 2; nt2++) {
            uint32_t r[4];
            ldmx4(r, sb + 4096 + boff[nt2]);
            wh[2 * nt2][0] = r[0]; wh[2 * nt2][1] = r[1];
            wh[2 * nt2 + 1][0] = r[2]; wh[2 * nt2 + 1][1] = r[3];
        }
#pragma unroll
        for (int mt = 0; mt < 4; mt++)
#pragma unroll
            for (int nt = 0; nt < 4; nt++)
                mma16816(acc[mt][nt], ah[mt], wh[nt]);
        __syncthreads();
        if (c + 3 < NC) { load_stage(c + 3, st); cp_commit(); }
    }

    // ---- epilogue: bias, fp32 store, BN stats ----
    float bv[8];
#pragma unroll
    for (int nt = 0; nt < 4; nt++) {
        int gn = n0 + wn * 32 + nt * 8 + 2 * (lane & 3);
        bv[2 * nt] = bias[gn];
        bv[2 * nt + 1] = bias[gn + 1];
    }
    float colsum[8], colsq[8];
#pragma unroll
    for (int j = 0; j < 8; j++) { colsum[j] = 0.f; colsq[j] = 0.f; }

#pragma unroll
    for (int mt = 0; mt < 4; mt++) {
        int gm = m0 + wm * 64 + mt * 16 + (lane >> 2);
#pragma unroll
        for (int nt = 0; nt < 4; nt++) {
            int gn = n0 + wn * 32 + nt * 8 + 2 * (lane & 3);
            float c0 = acc[mt][nt][0] + bv[2 * nt];
            float c1 = acc[mt][nt][1] + bv[2 * nt + 1];
            float c2 = acc[mt][nt][2] + bv[2 * nt];
            float c3 = acc[mt][nt][3] + bv[2 * nt + 1];
            *(float2*)(C + (size_t)gm * 256 + gn)       = make_float2(c0, c1);
            *(float2*)(C + (size_t)(gm + 8) * 256 + gn) = make_float2(c2, c3);
            colsum[2 * nt]     += c0 + c2;
            colsum[2 * nt + 1] += c1 + c3;
            colsq[2 * nt]      += c0 * c0 + c2 * c2;
            colsq[2 * nt + 1]  += c1 * c1 + c3 * c3;
        }
    }

    __syncthreads();                    // stage smem reusable now
    float* ssum = (float*)smem;         // 128 floats
    float* ssq  = ssum + 128;           // 128 floats
    ((float*)smem)[tid] = 0.f;          // zero 256 floats
    __syncthreads();
#pragma unroll
    for (int nt = 0; nt < 4; nt++) {
        int cl = wn * 32 + nt * 8 + 2 * (lane & 3);
        atomicAdd(&ssum[cl],     colsum[2 * nt]);
        atomicAdd(&ssum[cl + 1], colsum[2 * nt + 1]);
        atomicAdd(&ssq[cl],      colsq[2 * nt]);
        atomicAdd(&ssq[cl + 1],  colsq[2 * nt + 1]);
    }
    __syncthreads();
    if (tid < 128) {
        atomicAdd(&gsum[n0 + tid], ssum[tid]);
        atomicAdd(&gsq[n0 + tid],  ssq[tid]);
    }
}

__global__ void __launch_bounds__(256) gemm0_kernel(const float* __restrict__ b0) {
    gemm_body<K0_>(g_A, g_W0h, b0, g_y0, g_sum0, g_sq0);
}
__global__ void __launch_bounds__(256) gemm1k_kernel(const float* __restrict__ b1) {
    gemm_body<M0_>(g_Z, g_W1h, b1, g_y1, g_sum1, g_sq1);
}

// ---------------- kernel: finalize BN stats -> scale/shift ------------------
__global__ void finalize0_kernel(const float* __restrict__ gamma,
                                 const float* __restrict__ beta) {
    int c = threadIdx.x;
    float cnt = (float)MTOT;
    float mean = g_sum0[c] / cnt;
    float var = g_sq0[c] / cnt - mean * mean;
    float inv = rsqrtf(var + 1e-5f);
    float sc = gamma[c] * inv;
    g_scale0[c] = sc;
    g_shift0[c] = beta[c] - mean * sc;
}
__global__ void finalize1_kernel(const float* __restrict__ gamma,
                                 const float* __restrict__ beta) {
    int c = threadIdx.x;
    float cnt = (float)MTOT;
    float mean = g_sum1[c] / cnt;
    float var = g_sq1[c] / cnt - mean * mean;
    float inv = rsqrtf(var + 1e-5f);
    float sc = gamma[c] * inv;
    g_scale1[c] = sc;
    g_shift1[c] = beta[c] - mean * sc;
}

// ---------------- kernel: BN + ReLU on y0 -> fp16 Z -------------------------
__global__ void bnrelu0_kernel() {
    size_t i4 = (size_t)blockIdx.x * 256 + threadIdx.x;   // float4 index
    float4 v = ((const float4*)g_y0)[i4];
    int c = ((int)(i4 & 63)) * 4;                          // 64 float4 per 256-ch row
    float x0 = fmaxf(v.x * g_scale0[c + 0] + g_shift0[c + 0], 0.f);
    float x1 = fmaxf(v.y * g_scale0[c + 1] + g_shift0[c + 1], 0.f);
    float x2 = fmaxf(v.z * g_scale0[c + 2] + g_shift0[c + 2], 0.f);
    float x3 = fmaxf(v.w * g_scale0[c + 3] + g_shift0[c + 3], 0.f);
    ((uint2*)g_Z)[i4] = make_uint2(packh(x0, x1), packh(x2, x3));
}

// ---------------- kernel: BN + ReLU + transpose -> out [B, M1, N] -----------
__global__ void bnrelu1_transpose_kernel(float* __restrict__ out) {
    __shared__ float tile[32][33];
    int b = blockIdx.z;
    int n0 = blockIdx.x * 32, o0 = blockIdx.y * 32;
    int tx = threadIdx.x, ty = threadIdx.y;
    float sc = g_scale1[o0 + tx];
    float sh = g_shift1[o0 + tx];
    const float* ip = g_y1 + (size_t)b * N_ * M1_;
#pragma unroll
    for (int i = 0; i < 4; i++) {
        int r = ty + i * 8;
        float v = ip[(size_t)(n0 + r) * M1_ + o0 + tx];
        tile[r][tx] = fmaxf(v * sc + sh, 0.f);
    }
    __syncthreads();
    float* op = out + (size_t)b * M1_ * N_;
#pragma unroll
    for (int i = 0; i < 4; i++) {
        int r = ty + i * 8;
        op[(size_t)(o0 + r) * N_ + n0 + tx] = tile[tx][r];
    }
}

// ---------------- launch ----------------------------------------------------
extern "C" void kernel_launch(void* const* d_in, const int* in_sizes, int n_in,
                              void* d_out, int out_size) {
    const float* xyz1 = (const float*)d_in[0];
    const float* xyz2 = (const float*)d_in[1];
    const float* p1   = (const float*)d_in[2];
    const float* p2   = (const float*)d_in[3];
    const float* w0   = (const float*)d_in[4];
    const float* b0   = (const float*)d_in[5];
    const float* g0   = (const float*)d_in[6];
    const float* be0  = (const float*)d_in[7];
    const float* w1   = (const float*)d_in[8];
    const float* b1   = (const float*)d_in[9];
    const float* g1   = (const float*)d_in[10];
    const float* be1  = (const float*)d_in[11];
    float* out = (float*)d_out;

    zero_stats_kernel<<<1, 256>>>();
    convw0_kernel<<<(M0_ * K0_ + 255) / 256, 256>>>(w0);
    convw1_kernel<<<(M1_ * M0_ + 255) / 256, 256>>>(w1);
    transpose_p1_kernel<<<dim3(N_ / 32, C1_ / 32, B_), dim3(32, 8)>>>(p1);
    transpose_p2_kernel<<<dim3(S_ / 32, C2_ / 32, B_), dim3(32, 8)>>>(p2);
    knn_kernel<<<dim3(N_ / 128, B_), 128>>>(xyz1, xyz2);
    gather_kernel<<<dim3(N_ / 8, B_), 256>>>();

    gemm0_kernel<<<dim3(MTOT / 128, M0_ / 128), 256>>>(b0);
    finalize0_kernel<<<1, 256>>>(g0, be0);
    bnrelu0_kernel<<<(unsigned)((size_t)MTOT * M0_ / 4 / 256), 256>>>();

    gemm1k_kernel<<<dim3(MTOT / 128, M1_ / 128), 256>>>(b1);
    finalize1_kernel<<<1, 256>>>(g1, be1);
    bnrelu1_transpose_kernel<<<dim3(N_ / 32, M1_ / 32, B_), dim3(32, 8)>>>(out);
}

// round 15
// speedup vs baseline: 2.3125x; 1.0248x over previous
#include <cuda_runtime.h>
#include <cuda_fp16.h>
#include <cstdint>
#include <cstddef>

// Problem dims (fixed by the dataset)
#define B_   16
#define N_   4096
#define S_   1024
#define C1_  256
#define C2_  256
#define K0_  512      // C1+C2
#define M0_  256
#define M1_  256
#define MTOT (B_*N_)  // 65536 rows (b*N+n)

// ---------------- scratch (static device globals; no cudaMalloc allowed) ----
__device__ __align__(16) __half g_A[(size_t)MTOT * K0_];    // 64 MB concat activations fp16
__device__ __align__(16) __half g_Z[(size_t)MTOT * M0_];    // 32 MB layer-1 input fp16
__device__ __align__(16) __half g_W0h[(size_t)M0_ * K0_];
__device__ __align__(16) __half g_W1h[(size_t)M1_ * M0_];
__device__ __align__(16) __half g_y0[(size_t)MTOT * M0_];   // layer-0 pre-BN fp16
__device__ __align__(16) __half g_y1[(size_t)MTOT * M1_];   // layer-1 pre-BN fp16
__device__ float g_p2t[(size_t)B_ * S_ * C2_];    // [B, S, C2]  transposed points2
__device__ int   g_idx[(size_t)B_ * N_ * 3];
__device__ float g_w[(size_t)B_ * N_ * 3];
__device__ float g_sum0[M0_], g_sq0[M0_], g_sum1[M1_], g_sq1[M1_];
__device__ float g_scale0[M0_], g_shift0[M0_], g_scale1[M1_], g_shift1[M1_];

// ---------------- small helpers ---------------------------------------------
static __device__ __forceinline__ uint32_t sm32(const void* p) {
    return (uint32_t)__cvta_generic_to_shared(p);
}
static __device__ __forceinline__ uint32_t packh(float a, float b) {
    __half2 t = __floats2half2_rn(a, b);
    return *reinterpret_cast<uint32_t*>(&t);
}
static __device__ __forceinline__ void cpa16(uint32_t dst, const void* src) {
    asm volatile("cp.async.cg.shared.global [%0], [%1], 16;" :: "r"(dst), "l"(src));
}
static __device__ __forceinline__ void cp_commit() {
    asm volatile("cp.async.commit_group;" ::: "memory");
}
template <int n>
static __device__ __forceinline__ void cp_wait() {
    asm volatile("cp.async.wait_group %0;" :: "n"(n) : "memory");
}
// ldmatrix x4 (b16, non-transposed)
static __device__ __forceinline__ void ldmx4(uint32_t r[4], uint32_t addr) {
    asm volatile("ldmatrix.sync.aligned.m8n8.x4.shared.b16 {%0,%1,%2,%3}, [%4];"
                 : "=r"(r[0]), "=r"(r[1]), "=r"(r[2]), "=r"(r[3]) : "r"(addr));
}
// HMMA m16n8k16 fp16 -> f32 accumulate (base sm_80+ PTX, legal on compute_103)
static __device__ __forceinline__ void mma16816(float c[4], const uint32_t a[4],
                                                const uint32_t b[2]) {
    asm volatile(
        "mma.sync.aligned.m16n8k16.row.col.f32.f16.f16.f32 "
        "{%0,%1,%2,%3}, {%4,%5,%6,%7}, {%8,%9}, {%0,%1,%2,%3};"
        : "+f"(c[0]), "+f"(c[1]), "+f"(c[2]), "+f"(c[3])
        : "r"(a[0]), "r"(a[1]), "r"(a[2]), "r"(a[3]), "r"(b[0]), "r"(b[1]));
}
// swizzle for 32B rows (8-row atom spans 256B): XOR bit4 with bit7
static __device__ __forceinline__ uint32_t swz(uint32_t off) {
    return off ^ ((off >> 3) & 0x10);
}

// ---------------- kernel: prep (zero stats + both weight converts) ----------
__global__ void prep_kernel(const float* __restrict__ w0,
                            const float* __restrict__ w1) {
    int i = blockIdx.x * 256 + threadIdx.x;      // grid 512 blocks -> 131072
    if (i < 256) {
        g_sum0[i] = 0.f; g_sq0[i] = 0.f;
        g_sum1[i] = 0.f; g_sq1[i] = 0.f;
    }
    if (i < M0_ * K0_) g_W0h[i] = __float2half_rn(w0[i]);
    if (i < M1_ * M0_) g_W1h[i] = __float2half_rn(w1[i]);
}

// ---------------- kernel: transpose points1 [B,C1,N] -> g_A[:, 0:256] -------
__global__ void transpose_p1_kernel(const float* __restrict__ p1) {
    __shared__ float tile[32][33];               // tile[c][n]
    int b = blockIdx.z;
    int n0 = blockIdx.x * 32, c0 = blockIdx.y * 32;
    int tx = threadIdx.x, ty = threadIdx.y;      // (32, 8)
    const float* ip = p1 + (size_t)b * C1_ * N_;
#pragma unroll
    for (int i = 0; i < 4; i++) {
        int r = ty + i * 8;
        tile[r][tx] = ip[(size_t)(c0 + r) * N_ + n0 + tx];
    }
    __syncthreads();
    int t = ty * 32 + tx;                        // 0..255
    int cp = t & 15;                             // channel pair 0..15
    int r0r = t >> 4;                            // 0..15
    size_t rb = (size_t)b * N_;
#pragma unroll
    for (int i = 0; i < 2; i++) {
        int row = r0r + i * 16;
        uint32_t v = packh(tile[2 * cp][row], tile[2 * cp + 1][row]);
        *reinterpret_cast<uint32_t*>(g_A + (rb + n0 + row) * K0_ + c0 + 2 * cp) = v;
    }
}

// ---------------- kernel: transpose points2 [B,C2,S] -> p2t [B,S,C2] --------
__global__ void transpose_p2_kernel(const float* __restrict__ p2) {
    __shared__ float tile[32][33];
    int b = blockIdx.z;
    int s0 = blockIdx.x * 32, c0 = blockIdx.y * 32;
    int tx = threadIdx.x, ty = threadIdx.y;
    const float* ip = p2 + (size_t)b * C2_ * S_;
    float* op = g_p2t + (size_t)b * S_ * C2_;
#pragma unroll
    for (int i = 0; i < 4; i++) {
        int r = ty + i * 8;
        tile[r][tx] = ip[(size_t)(c0 + r) * S_ + s0 + tx];
    }
    __syncthreads();
#pragma unroll
    for (int i = 0; i < 4; i++) {
        int r = ty + i * 8;
        op[(size_t)(s0 + r) * C2_ + c0 + tx] = tile[tx][r];
    }
}

// ---------------- kernel: 3-NN, 4 independent chains for ILP ----------------
__global__ void knn_kernel(const float* __restrict__ xyz1,
                           const float* __restrict__ xyz2) {
    __shared__ float4 s4[S_];
    int b = blockIdx.y;
    const float* x2 = xyz2 + (size_t)b * 3 * S_;
    for (int j = threadIdx.x; j < S_; j += 128) {
        float a = x2[j], c = x2[S_ + j], d = x2[2 * S_ + j];
        s4[j] = make_float4(a, c, d, a * a + c * c + d * d);
    }
    __syncthreads();

    int n = blockIdx.x * 128 + threadIdx.x;
    const float* x1 = xyz1 + (size_t)b * 3 * N_;
    float px = x1[n], py = x1[N_ + n], pz = x1[2 * N_ + n];
    float n1 = px * px + py * py + pz * pz;

    float cd0[4], cd1[4], cd2[4];
    int   ci0[4], ci1[4], ci2[4];
#pragma unroll
    for (int c = 0; c < 4; c++) {
        cd0[c] = cd1[c] = cd2[c] = 1e30f;
        ci0[c] = ci1[c] = ci2[c] = 0;
    }
    for (int t = 0; t < 256; t++) {
#pragma unroll
        for (int c = 0; c < 4; c++) {
            int s = t + c * 256;
            float4 w = s4[s];
            float dot = px * w.x + py * w.y + pz * w.z;
            float d = n1 + w.w - 2.f * dot;
            if (d < cd2[c]) {
                if (d < cd1[c]) {
                    cd2[c] = cd1[c]; ci2[c] = ci1[c];
                    if (d < cd0[c]) { cd1[c] = cd0[c]; ci1[c] = ci0[c]; cd0[c] = d; ci0[c] = s; }
                    else            { cd1[c] = d;      ci1[c] = s; }
                } else { cd2[c] = d; ci2[c] = s; }
            }
        }
    }
    // merge 12 candidates
    float d0 = 1e30f, d1 = 1e30f, d2 = 1e30f;
    int i0 = 0, i1 = 0, i2 = 0;
    auto ins = [&](float d, int i) {
        if (d < d2) {
            if (d < d1) {
                d2 = d1; i2 = i1;
                if (d < d0) { d1 = d0; i1 = i0; d0 = d; i0 = i; }
                else        { d1 = d;  i1 = i; }
            } else { d2 = d; i2 = i; }
        }
    };
#pragma unroll
    for (int c = 0; c < 4; c++) { ins(cd0[c], ci0[c]); ins(cd1[c], ci1[c]); ins(cd2[c], ci2[c]); }

    float r0 = 1.f / (d0 + 1e-8f);
    float r1 = 1.f / (d1 + 1e-8f);
    float r2 = 1.f / (d2 + 1e-8f);
    float rs = r0 + r1 + r2;
    size_t base = ((size_t)b * N_ + n) * 3;
    g_idx[base] = i0; g_idx[base + 1] = i1; g_idx[base + 2] = i2;
    g_w[base] = r0 / rs; g_w[base + 1] = r1 / rs; g_w[base + 2] = r2 / rs;
}

// ---------------- kernel: weighted gather -> g_A[:, 256:512] ----------------
__global__ void gather_kernel() {
    int b = blockIdx.y;
    int warp = threadIdx.x >> 5, lane = threadIdx.x & 31;
    int n = blockIdx.x * 8 + warp;
    size_t base = ((size_t)b * N_ + n) * 3;
    int i0 = g_idx[base], i1 = g_idx[base + 1], i2 = g_idx[base + 2];
    float w0 = g_w[base], w1 = g_w[base + 1], w2 = g_w[base + 2];
    const float4* r0 = (const float4*)(g_p2t + ((size_t)b * S_ + i0) * C2_);
    const float4* r1 = (const float4*)(g_p2t + ((size_t)b * S_ + i1) * C2_);
    const float4* r2 = (const float4*)(g_p2t + ((size_t)b * S_ + i2) * C2_);
    size_t rowe = ((size_t)b * N_ + n) * K0_ + C1_;
#pragma unroll
    for (int t = 0; t < 2; t++) {
        int c = lane + t * 32;                 // 64 float4 per 256-ch half
        float4 a = r0[c], bb = r1[c], cc = r2[c];
        float ox = w0 * a.x + w1 * bb.x + w2 * cc.x;
        float oy = w0 * a.y + w1 * bb.y + w2 * cc.y;
        float oz = w0 * a.z + w1 * bb.z + w2 * cc.z;
        float ow = w0 * a.w + w1 * bb.w + w2 * cc.w;
        *reinterpret_cast<uint2*>(g_A + rowe + 4 * c) =
            make_uint2(packh(ox, oy), packh(oz, ow));
    }
}

// ---------------- HMMA fp16 GEMM: C(fp16) = A[M,K]*W[256,K]^T + bias --------
// CTA tile 128x128, 8 warps (2x4), warp tile 64x32, BK=16, 3-stage cp.async.
// Grid (n, m): consecutive CTAs share the A tile -> L2 reuse.
// Accumulates per-output-channel sum/sumsq (BN training stats) in fp32.
template <int KDIM>
static __device__ __forceinline__ void gemm_body(
    const __half* __restrict__ A, const __half* __restrict__ Wh,
    const float* __restrict__ bias, __half* __restrict__ C,
    float* __restrict__ gsum, float* __restrict__ gsq) {
    constexpr int NC = KDIM / 16;              // 32 or 16 k-steps
    __shared__ __align__(1024) char smem[3 * 8192];    // 3 stages x (A|W 4KB each)

    int tid = threadIdx.x, lane = tid & 31, wid = tid >> 5;
    int wm = wid & 1, wn = wid >> 1;           // 2 x 4 warp grid
    int n0 = blockIdx.x * 128, m0 = blockIdx.y * 128;

    const char* pA = (const char*)A;
    const char* pW = (const char*)Wh;
    const size_t rowb = (size_t)KDIM * 2;      // bytes per gmem row

    uint32_t smb = sm32(smem);

    // --- per-thread cp.async assignments (2 x 16B per stage) ---
    auto load_stage = [&](int c, int st) {
        uint32_t sb = smb + st * 8192;
        int kb = c * 32;                       // byte offset of k16 chunk
#pragma unroll
        for (int i = 0; i < 2; i++) {
            int idx = tid + i * 256;
            int part = idx >> 8, v = idx & 255;
            int row = v >> 1, seg = v & 1;
            uint32_t off = (uint32_t)(row * 32 + seg * 16);
            uint32_t dst = sb + part * 4096 + swz(off);
            if (part == 0)
                cpa16(dst, pA + (size_t)(m0 + row) * rowb + kb + seg * 16);
            else
                cpa16(dst, pW + (size_t)(n0 + row) * rowb + kb + seg * 16);
        }
    };

    // --- ldmatrix per-lane offsets (within a 4KB part region) ---
    uint32_t aoff[4], boff[2];
    {
        int arow = wm * 64 + (lane & 15);
        int akc = (lane >> 4) * 8;             // lanes 16-31 read k+8 matrices
#pragma unroll
        for (int mt = 0; mt < 4; mt++)
            aoff[mt] = swz((uint32_t)((arow + mt * 16) * 32 + akc * 2));
        int brow = wn * 32 + ((lane >> 4) << 3) + (lane & 7);
        int bkc = ((lane >> 3) & 1) * 8;
#pragma unroll
        for (int nt2 = 0; nt2 < 2; nt2++)
            boff[nt2] = swz((uint32_t)((brow + nt2 * 16) * 32 + bkc * 2));
    }

    float acc[4][4][4];
#pragma unroll
    for (int i = 0; i < 4; i++)
#pragma unroll
        for (int j = 0; j < 4; j++)
#pragma unroll
            for (int q = 0; q < 4; q++) acc[i][j][q] = 0.f;

    load_stage(0, 0); cp_commit();
    load_stage(1, 1); cp_commit();
    load_stage(2, 2); cp_commit();

#pragma unroll 1
    for (int c = 0; c < NC; c++) {
        int st = c % 3;
        if (c < NC - 2)       cp_wait<2>();
        else if (c == NC - 2) cp_wait<1>();
        else                  cp_wait<0>();
        __syncthreads();

        uint32_t sb = smb + st * 8192;
        uint32_t ah[4][4], wh[4][2];
#pragma unroll
        for (int mt = 0; mt < 4; mt++) ldmx4(ah[mt], sb + aoff[mt]);
#pragma unroll
        for (int nt2 = 0; nt2 < 2; nt2++) {
            uint32_t r[4];
            ldmx4(r, sb + 4096 + boff[nt2]);
            wh[2 * nt2][0] = r[0]; wh[2 * nt2][1] = r[1];
            wh[2 * nt2 + 1][0] = r[2]; wh[2 * nt2 + 1][1] = r[3];
        }
#pragma unroll
        for (int mt = 0; mt < 4; mt++)
#pragma unroll
            for (int nt = 0; nt < 4; nt++)
                mma16816(acc[mt][nt], ah[mt], wh[nt]);
        __syncthreads();
        if (c + 3 < NC) { load_stage(c + 3, st); cp_commit(); }
    }

    // ---- epilogue: bias, fp16 store, BN stats (from fp32 values) ----
    float bv[8];
#pragma unroll
    for (int nt = 0; nt < 4; nt++) {
        int gn = n0 + wn * 32 + nt * 8 + 2 * (lane & 3);
        bv[2 * nt] = bias[gn];
        bv[2 * nt + 1] = bias[gn + 1];
    }
    float colsum[8], colsq[8];
#pragma unroll
    for (int j = 0; j < 8; j++) { colsum[j] = 0.f; colsq[j] = 0.f; }

#pragma unroll
    for (int mt = 0; mt < 4; mt++) {
        int gm = m0 + wm * 64 + mt * 16 + (lane >> 2);
#pragma unroll
        for (int nt = 0; nt < 4; nt++) {
            int gn = n0 + wn * 32 + nt * 8 + 2 * (lane & 3);
            float c0 = acc[mt][nt][0] + bv[2 * nt];
            float c1 = acc[mt][nt][1] + bv[2 * nt + 1];
            float c2 = acc[mt][nt][2] + bv[2 * nt];
            float c3 = acc[mt][nt][3] + bv[2 * nt + 1];
            *reinterpret_cast<uint32_t*>(C + (size_t)gm * 256 + gn)       = packh(c0, c1);
            *reinterpret_cast<uint32_t*>(C + (size_t)(gm + 8) * 256 + gn) = packh(c2, c3);
            colsum[2 * nt]     += c0 + c2;
            colsum[2 * nt + 1] += c1 + c3;
            colsq[2 * nt]      += c0 * c0 + c2 * c2;
            colsq[2 * nt + 1]  += c1 * c1 + c3 * c3;
        }
    }

    __syncthreads();                    // stage smem reusable now
    float* ssum = (float*)smem;         // 128 floats
    float* ssq  = ssum + 128;           // 128 floats
    ((float*)smem)[tid] = 0.f;          // zero 256 floats
    __syncthreads();
#pragma unroll
    for (int nt = 0; nt < 4; nt++) {
        int cl = wn * 32 + nt * 8 + 2 * (lane & 3);
        atomicAdd(&ssum[cl],     colsum[2 * nt]);
        atomicAdd(&ssum[cl + 1], colsum[2 * nt + 1]);
        atomicAdd(&ssq[cl],      colsq[2 * nt]);
        atomicAdd(&ssq[cl + 1],  colsq[2 * nt + 1]);
    }
    __syncthreads();
    if (tid < 128) {
        atomicAdd(&gsum[n0 + tid], ssum[tid]);
        atomicAdd(&gsq[n0 + tid],  ssq[tid]);
    }
}

__global__ void __launch_bounds__(256) gemm0_kernel(const float* __restrict__ b0) {
    gemm_body<K0_>(g_A, g_W0h, b0, g_y0, g_sum0, g_sq0);
}
__global__ void __launch_bounds__(256) gemm1k_kernel(const float* __restrict__ b1) {
    gemm_body<M0_>(g_Z, g_W1h, b1, g_y1, g_sum1, g_sq1);
}

// ---------------- kernel: finalize BN stats -> scale/shift ------------------
__global__ void finalize0_kernel(const float* __restrict__ gamma,
                                 const float* __restrict__ beta) {
    int c = threadIdx.x;
    float cnt = (float)MTOT;
    float mean = g_sum0[c] / cnt;
    float var = g_sq0[c] / cnt - mean * mean;
    float inv = rsqrtf(var + 1e-5f);
    float sc = gamma[c] * inv;
    g_scale0[c] = sc;
    g_shift0[c] = beta[c] - mean * sc;
}
__global__ void finalize1_kernel(const float* __restrict__ gamma,
                                 const float* __restrict__ beta) {
    int c = threadIdx.x;
    float cnt = (float)MTOT;
    float mean = g_sum1[c] / cnt;
    float var = g_sq1[c] / cnt - mean * mean;
    float inv = rsqrtf(var + 1e-5f);
    float sc = gamma[c] * inv;
    g_scale1[c] = sc;
    g_shift1[c] = beta[c] - mean * sc;
}

// ---------------- kernel: BN + ReLU on fp16 y0 -> fp16 Z --------------------
__global__ void bnrelu0_kernel() {
    size_t i4 = (size_t)blockIdx.x * 256 + threadIdx.x;   // group of 4 halves
    uint2 v = ((const uint2*)g_y0)[i4];
    __half2 h01 = *reinterpret_cast<__half2*>(&v.x);
    __half2 h23 = *reinterpret_cast<__half2*>(&v.y);
    int c = ((int)(i4 & 63)) * 4;                          // 64 groups per 256-ch row
    float x0 = fmaxf(__low2float(h01)  * g_scale0[c + 0] + g_shift0[c + 0], 0.f);
    float x1 = fmaxf(__high2float(h01) * g_scale0[c + 1] + g_shift0[c + 1], 0.f);
    float x2 = fmaxf(__low2float(h23)  * g_scale0[c + 2] + g_shift0[c + 2], 0.f);
    float x3 = fmaxf(__high2float(h23) * g_scale0[c + 3] + g_shift0[c + 3], 0.f);
    ((uint2*)g_Z)[i4] = make_uint2(packh(x0, x1), packh(x2, x3));
}

// ---------------- kernel: BN + ReLU + transpose -> out [B, M1, N] -----------
__global__ void bnrelu1_transpose_kernel(float* __restrict__ out) {
    __shared__ float tile[32][33];
    int b = blockIdx.z;
    int n0 = blockIdx.x * 32, o0 = blockIdx.y * 32;
    int tx = threadIdx.x, ty = threadIdx.y;
    float sc = g_scale1[o0 + tx];
    float sh = g_shift1[o0 + tx];
    const __half* ip = g_y1 + (size_t)b * N_ * M1_;
#pragma unroll
    for (int i = 0; i < 4; i++) {
        int r = ty + i * 8;
        float v = __half2float(ip[(size_t)(n0 + r) * M1_ + o0 + tx]);
        tile[r][tx] = fmaxf(v * sc + sh, 0.f);
    }
    __syncthreads();
    float* op = out + (size_t)b * M1_ * N_;
#pragma unroll
    for (int i = 0; i < 4; i++) {
        int r = ty + i * 8;
        op[(size_t)(o0 + r) * N_ + n0 + tx] = tile[tx][r];
    }
}

// ---------------- launch ----------------------------------------------------
extern "C" void kernel_launch(void* const* d_in, const int* in_sizes, int n_in,
                              void* d_out, int out_size) {
    const float* xyz1 = (const float*)d_in[0];
    const float* xyz2 = (const float*)d_in[1];
    const float* p1   = (const float*)d_in[2];
    const float* p2   = (const float*)d_in[3];
    const float* w0   = (const float*)d_in[4];
    const float* b0   = (const float*)d_in[5];
    const float* g0   = (const float*)d_in[6];
    const float* be0  = (const float*)d_in[7];
    const float* w1   = (const float*)d_in[8];
    const float* b1   = (const float*)d_in[9];
    const float* g1   = (const float*)d_in[10];
    const float* be1  = (const float*)d_in[11];
    float* out = (float*)d_out;

    prep_kernel<<<512, 256>>>(w0, w1);
    transpose_p1_kernel<<<dim3(N_ / 32, C1_ / 32, B_), dim3(32, 8)>>>(p1);
    transpose_p2_kernel<<<dim3(S_ / 32, C2_ / 32, B_), dim3(32, 8)>>>(p2);
    knn_kernel<<<dim3(N_ / 128, B_), 128>>>(xyz1, xyz2);
    gather_kernel<<<dim3(N_ / 8, B_), 256>>>();

    gemm0_kernel<<<dim3(M0_ / 128, MTOT / 128), 256>>>(b0);
    finalize0_kernel<<<1, 256>>>(g0, be0);
    bnrelu0_kernel<<<(unsigned)((size_t)MTOT * M0_ / 4 / 256), 256>>>();

    gemm1k_kernel<<<dim3(M1_ / 128, MTOT / 128), 256>>>(b1);
    finalize1_kernel<<<1, 256>>>(g1, be1);
    bnrelu1_transpose_kernel<<<dim3(N_ / 32, M1_ / 32, B_), dim3(32, 8)>>>(out);
}

// round 16
// speedup vs baseline: 2.4402x; 1.0552x over previous
#include <cuda_runtime.h>
#include <cuda_fp16.h>
#include <cstdint>
#include <cstddef>

// Problem dims (fixed by the dataset)
#define B_   16
#define N_   4096
#define S_   1024
#define C1_  256
#define C2_  256
#define K0_  512      // C1+C2
#define M0_  256
#define M1_  256
#define MTOT (B_*N_)  // 65536 rows (b*N+n)

// ---------------- scratch (static device globals; no cudaMalloc allowed) ----
__device__ __align__(16) __half g_A[(size_t)MTOT * K0_];    // 64 MB concat activations fp16
__device__ __align__(16) __half g_Z[(size_t)MTOT * M0_];    // 32 MB layer-1 input fp16
__device__ __align__(16) __half g_W0h[(size_t)M0_ * K0_];
__device__ __align__(16) __half g_W1h[(size_t)M1_ * M0_];
__device__ __align__(16) __half g_y0[(size_t)MTOT * M0_];   // layer-0 pre-BN fp16
__device__ __align__(16) __half g_y1[(size_t)MTOT * M1_];   // layer-1 pre-BN fp16
__device__ float g_p2t[(size_t)B_ * S_ * C2_];    // [B, S, C2]  transposed points2
__device__ int   g_idx[(size_t)B_ * N_ * 3];
__device__ float g_w[(size_t)B_ * N_ * 3];
__device__ float g_sum0[M0_], g_sq0[M0_], g_sum1[M1_], g_sq1[M1_];
__device__ float g_scale0[M0_], g_shift0[M0_], g_scale1[M1_], g_shift1[M1_];

// ---------------- small helpers ---------------------------------------------
static __device__ __forceinline__ uint32_t sm32(const void* p) {
    return (uint32_t)__cvta_generic_to_shared(p);
}
static __device__ __forceinline__ uint32_t packh(float a, float b) {
    __half2 t = __floats2half2_rn(a, b);
    return *reinterpret_cast<uint32_t*>(&t);
}
static __device__ __forceinline__ void cpa16(uint32_t dst, const void* src) {
    asm volatile("cp.async.cg.shared.global [%0], [%1], 16;" :: "r"(dst), "l"(src));
}
static __device__ __forceinline__ void cp_commit() {
    asm volatile("cp.async.commit_group;" ::: "memory");
}
template <int n>
static __device__ __forceinline__ void cp_wait() {
    asm volatile("cp.async.wait_group %0;" :: "n"(n) : "memory");
}
// ldmatrix x4 (b16, non-transposed)
static __device__ __forceinline__ void ldmx4(uint32_t r[4], uint32_t addr) {
    asm volatile("ldmatrix.sync.aligned.m8n8.x4.shared.b16 {%0,%1,%2,%3}, [%4];"
                 : "=r"(r[0]), "=r"(r[1]), "=r"(r[2]), "=r"(r[3]) : "r"(addr));
}
// HMMA m16n8k16 fp16 -> f32 accumulate (base sm_80+ PTX, legal on compute_103)
static __device__ __forceinline__ void mma16816(float c[4], const uint32_t a[4],
                                                const uint32_t b[2]) {
    asm volatile(
        "mma.sync.aligned.m16n8k16.row.col.f32.f16.f16.f32 "
        "{%0,%1,%2,%3}, {%4,%5,%6,%7}, {%8,%9}, {%0,%1,%2,%3};"
        : "+f"(c[0]), "+f"(c[1]), "+f"(c[2]), "+f"(c[3])
        : "r"(a[0]), "r"(a[1]), "r"(a[2]), "r"(a[3]), "r"(b[0]), "r"(b[1]));
}
// swizzle for 32B rows (8-row atom spans 256B): XOR bit4 with bit7
static __device__ __forceinline__ uint32_t swz(uint32_t off) {
    return off ^ ((off >> 3) & 0x10);
}

// ---------------- kernel: prep (zero stats + both weight converts) ----------
__global__ void prep_kernel(const float* __restrict__ w0,
                            const float* __restrict__ w1) {
    int i = blockIdx.x * 256 + threadIdx.x;      // grid 512 blocks -> 131072
    if (i < 256) {
        g_sum0[i] = 0.f; g_sq0[i] = 0.f;
        g_sum1[i] = 0.f; g_sq1[i] = 0.f;
    }
    if (i < M0_ * K0_) g_W0h[i] = __float2half_rn(w0[i]);
    if (i < M1_ * M0_) g_W1h[i] = __float2half_rn(w1[i]);
}

// ---------------- kernel: transpose points1 [B,C1,N] -> g_A[:, 0:256] -------
__global__ void transpose_p1_kernel(const float* __restrict__ p1) {
    __shared__ float tile[32][33];               // tile[c][n]
    int b = blockIdx.z;
    int n0 = blockIdx.x * 32, c0 = blockIdx.y * 32;
    int tx = threadIdx.x, ty = threadIdx.y;      // (32, 8)
    const float* ip = p1 + (size_t)b * C1_ * N_;
#pragma unroll
    for (int i = 0; i < 4; i++) {
        int r = ty + i * 8;
        tile[r][tx] = ip[(size_t)(c0 + r) * N_ + n0 + tx];
    }
    __syncthreads();
    int t = ty * 32 + tx;                        // 0..255
    int cp = t & 15;                             // channel pair 0..15
    int r0r = t >> 4;                            // 0..15
    size_t rb = (size_t)b * N_;
#pragma unroll
    for (int i = 0; i < 2; i++) {
        int row = r0r + i * 16;
        uint32_t v = packh(tile[2 * cp][row], tile[2 * cp + 1][row]);
        *reinterpret_cast<uint32_t*>(g_A + (rb + n0 + row) * K0_ + c0 + 2 * cp) = v;
    }
}

// ---------------- kernel: transpose points2 [B,C2,S] -> p2t [B,S,C2] --------
__global__ void transpose_p2_kernel(const float* __restrict__ p2) {
    __shared__ float tile[32][33];
    int b = blockIdx.z;
    int s0 = blockIdx.x * 32, c0 = blockIdx.y * 32;
    int tx = threadIdx.x, ty = threadIdx.y;
    const float* ip = p2 + (size_t)b * C2_ * S_;
    float* op = g_p2t + (size_t)b * S_ * C2_;
#pragma unroll
    for (int i = 0; i < 4; i++) {
        int r = ty + i * 8;
        tile[r][tx] = ip[(size_t)(c0 + r) * S_ + s0 + tx];
    }
    __syncthreads();
#pragma unroll
    for (int i = 0; i < 4; i++) {
        int r = ty + i * 8;
        op[(size_t)(s0 + r) * C2_ + c0 + tx] = tile[tx][r];
    }
}

// ---------------- kernel: 3-NN, S split 4-way across threads ----------------
// 512 threads = 128 points x 4 S-quarters; each thread scans 256 candidates
// (2 chains of 128), partial top-3 merged through smem.
__global__ void __launch_bounds__(512) knn_kernel(const float* __restrict__ xyz1,
                                                  const float* __restrict__ xyz2) {
    __shared__ float4 s4[S_];
    __shared__ float2 mrg[128][9];               // halves 1..3 publish top-3
    int b = blockIdx.y;
    const float* x2 = xyz2 + (size_t)b * 3 * S_;
    for (int j = threadIdx.x; j < S_; j += 512) {
        float a = x2[j], c = x2[S_ + j], d = x2[2 * S_ + j];
        s4[j] = make_float4(a, c, d, a * a + c * c + d * d);
    }
    __syncthreads();

    int tl = threadIdx.x & 127;                  // point within block
    int h  = threadIdx.x >> 7;                   // S-quarter 0..3
    int n  = blockIdx.x * 128 + tl;
    const float* x1 = xyz1 + (size_t)b * 3 * N_;
    float px = x1[n], py = x1[N_ + n], pz = x1[2 * N_ + n];
    float n1 = px * px + py * py + pz * pz;

    float cd0[2], cd1[2], cd2[2];
    int   ci0[2], ci1[2], ci2[2];
#pragma unroll
    for (int c = 0; c < 2; c++) {
        cd0[c] = cd1[c] = cd2[c] = 1e30f;
        ci0[c] = ci1[c] = ci2[c] = 0;
    }
    int sb = h * 256;
    for (int t = 0; t < 128; t++) {
#pragma unroll
        for (int c = 0; c < 2; c++) {
            int s = sb + t + c * 128;
            float4 w = s4[s];
            float dot = px * w.x + py * w.y + pz * w.z;
            float d = n1 + w.w - 2.f * dot;
            if (d < cd2[c]) {
                if (d < cd1[c]) {
                    cd2[c] = cd1[c]; ci2[c] = ci1[c];
                    if (d < cd0[c]) { cd1[c] = cd0[c]; ci1[c] = ci0[c]; cd0[c] = d; ci0[c] = s; }
                    else            { cd1[c] = d;      ci1[c] = s; }
                } else { cd2[c] = d; ci2[c] = s; }
            }
        }
    }
    // merge this thread's 2 chains (insert in increasing-s order)
    float d0 = 1e30f, d1 = 1e30f, d2 = 1e30f;
    int i0 = 0, i1 = 0, i2 = 0;
    auto ins = [&](float d, int i) {
        if (d < d2) {
            if (d < d1) {
                d2 = d1; i2 = i1;
                if (d < d0) { d1 = d0; i1 = i0; d0 = d; i0 = i; }
                else        { d1 = d;  i1 = i; }
            } else { d2 = d; i2 = i; }
        }
    };
#pragma unroll
    for (int c = 0; c < 2; c++) { ins(cd0[c], ci0[c]); ins(cd1[c], ci1[c]); ins(cd2[c], ci2[c]); }

    if (h) {
        int o = 3 * (h - 1);
        mrg[tl][o]     = make_float2(d0, __int_as_float(i0));
        mrg[tl][o + 1] = make_float2(d1, __int_as_float(i1));
        mrg[tl][o + 2] = make_float2(d2, __int_as_float(i2));
    }
    __syncthreads();
    if (h == 0) {
#pragma unroll
        for (int q = 0; q < 9; q++) {
            float2 v = mrg[tl][q];
            ins(v.x, __float_as_int(v.y));
        }
        float r0 = 1.f / (d0 + 1e-8f);
        float r1 = 1.f / (d1 + 1e-8f);
        float r2 = 1.f / (d2 + 1e-8f);
        float rs = r0 + r1 + r2;
        size_t base = ((size_t)b * N_ + n) * 3;
        g_idx[base] = i0; g_idx[base + 1] = i1; g_idx[base + 2] = i2;
        g_w[base] = r0 / rs; g_w[base + 1] = r1 / rs; g_w[base + 2] = r2 / rs;
    }
}

// ---------------- kernel: weighted gather -> g_A[:, 256:512] ----------------
__global__ void gather_kernel() {
    int b = blockIdx.y;
    int warp = threadIdx.x >> 5, lane = threadIdx.x & 31;
    int n = blockIdx.x * 8 + warp;
    size_t base = ((size_t)b * N_ + n) * 3;
    int i0 = g_idx[base], i1 = g_idx[base + 1], i2 = g_idx[base + 2];
    float w0 = g_w[base], w1 = g_w[base + 1], w2 = g_w[base + 2];
    const float4* r0 = (const float4*)(g_p2t + ((size_t)b * S_ + i0) * C2_);
    const float4* r1 = (const float4*)(g_p2t + ((size_t)b * S_ + i1) * C2_);
    const float4* r2 = (const float4*)(g_p2t + ((size_t)b * S_ + i2) * C2_);
    size_t rowe = ((size_t)b * N_ + n) * K0_ + C1_;
#pragma unroll
    for (int t = 0; t < 2; t++) {
        int c = lane + t * 32;                 // 64 float4 per 256-ch half
        float4 a = r0[c], bb = r1[c], cc = r2[c];
        float ox = w0 * a.x + w1 * bb.x + w2 * cc.x;
        float oy = w0 * a.y + w1 * bb.y + w2 * cc.y;
        float oz = w0 * a.z + w1 * bb.z + w2 * cc.z;
        float ow = w0 * a.w + w1 * bb.w + w2 * cc.w;
        *reinterpret_cast<uint2*>(g_A + rowe + 4 * c) =
            make_uint2(packh(ox, oy), packh(oz, ow));
    }
}

// ---------------- HMMA fp16 GEMM: C(fp16) = A[M,K]*W[256,K]^T + bias --------
// CTA tile 128x128, 8 warps (2x4), warp tile 64x32, BK=16, 3-stage cp.async.
// Grid (n, m): consecutive CTAs share the A tile -> L2 reuse.
// Accumulates per-output-channel sum/sumsq (BN training stats) in fp32.
template <int KDIM>
static __device__ __forceinline__ void gemm_body(
    const __half* __restrict__ A, const __half* __restrict__ Wh,
    const float* __restrict__ bias, __half* __restrict__ C,
    float* __restrict__ gsum, float* __restrict__ gsq) {
    constexpr int NC = KDIM / 16;              // 32 or 16 k-steps
    __shared__ __align__(1024) char smem[3 * 8192];    // 3 stages x (A|W 4KB each)

    int tid = threadIdx.x, lane = tid & 31, wid = tid >> 5;
    int wm = wid & 1, wn = wid >> 1;           // 2 x 4 warp grid
    int n0 = blockIdx.x * 128, m0 = blockIdx.y * 128;

    const char* pA = (const char*)A;
    const char* pW = (const char*)Wh;
    const size_t rowb = (size_t)KDIM * 2;      // bytes per gmem row

    uint32_t smb = sm32(smem);

    // --- per-thread cp.async assignments (2 x 16B per stage) ---
    auto load_stage = [&](int c, int st) {
        uint32_t sb = smb + st * 8192;
        int kb = c * 32;                       // byte offset of k16 chunk
#pragma unroll
        for (int i = 0; i < 2; i++) {
            int idx = tid + i * 256;
            int part = idx >> 8, v = idx & 255;
            int row = v >> 1, seg = v & 1;
            uint32_t off = (uint32_t)(row * 32 + seg * 16);
            uint32_t dst = sb + part * 4096 + swz(off);
            if (part == 0)
                cpa16(dst, pA + (size_t)(m0 + row) * rowb + kb + seg * 16);
            else
                cpa16(dst, pW + (size_t)(n0 + row) * rowb + kb + seg * 16);
        }
    };

    // --- ldmatrix per-lane offsets (within a 4KB part region) ---
    uint32_t aoff[4], boff[2];
    {
        int arow = wm * 64 + (lane & 15);
        int akc = (lane >> 4) * 8;             // lanes 16-31 read k+8 matrices
#pragma unroll
        for (int mt = 0; mt < 4; mt++)
            aoff[mt] = swz((uint32_t)((arow + mt * 16) * 32 + akc * 2));
        int brow = wn * 32 + ((lane >> 4) << 3) + (lane & 7);
        int bkc = ((lane >> 3) & 1) * 8;
#pragma unroll
        for (int nt2 = 0; nt2 < 2; nt2++)
            boff[nt2] = swz((uint32_t)((brow + nt2 * 16) * 32 + bkc * 2));
    }

    float acc[4][4][4];
#pragma unroll
    for (int i = 0; i < 4; i++)
#pragma unroll
        for (int j = 0; j < 4; j++)
#pragma unroll
            for (int q = 0; q < 4; q++) acc[i][j][q] = 0.f;

    load_stage(0, 0); cp_commit();
    load_stage(1, 1); cp_commit();
    load_stage(2, 2); cp_commit();

#pragma unroll 1
    for (int c = 0; c < NC; c++) {
        int st = c % 3;
        if (c < NC - 2)       cp_wait<2>();
        else if (c == NC - 2) cp_wait<1>();
        else                  cp_wait<0>();
        __syncthreads();

        uint32_t sb = smb + st * 8192;
        uint32_t ah[4][4], wh[4][2];
#pragma unroll
        for (int mt = 0; mt < 4; mt++) ldmx4(ah[mt], sb + aoff[mt]);
#pragma unroll
        for (int nt2 = 0; nt2 < 2; nt2++) {
            uint32_t r[4];
            ldmx4(r, sb + 4096 + boff[nt2]);
            wh[2 * nt2][0] = r[0]; wh[2 * nt2][1] = r[1];
            wh[2 * nt2 + 1][0] = r[2]; wh[2 * nt2 + 1][1] = r[3];
        }
#pragma unroll
        for (int mt = 0; mt < 4; mt++)
#pragma unroll
            for (int nt = 0; nt < 4; nt++)
                mma16816(acc[mt][nt], ah[mt], wh[nt]);
        __syncthreads();
        if (c + 3 < NC) { load_stage(c + 3, st); cp_commit(); }
    }

    // ---- epilogue: bias, fp16 store, BN stats (from fp32 values) ----
    float bv[8];
#pragma unroll
    for (int nt = 0; nt < 4; nt++) {
        int gn = n0 + wn * 32 + nt * 8 + 2 * (lane & 3);
        bv[2 * nt] = bias[gn];
        bv[2 * nt + 1] = bias[gn + 1];
    }
    float colsum[8], colsq[8];
#pragma unroll
    for (int j = 0; j < 8; j++) { colsum[j] = 0.f; colsq[j] = 0.f; }

#pragma unroll
    for (int mt = 0; mt < 4; mt++) {
        int gm = m0 + wm * 64 + mt * 16 + (lane >> 2);
#pragma unroll
        for (int nt = 0; nt < 4; nt++) {
            int gn = n0 + wn * 32 + nt * 8 + 2 * (lane & 3);
            float c0 = acc[mt][nt][0] + bv[2 * nt];
            float c1 = acc[mt][nt][1] + bv[2 * nt + 1];
            float c2 = acc[mt][nt][2] + bv[2 * nt];
            float c3 = acc[mt][nt][3] + bv[2 * nt + 1];
            *reinterpret_cast<uint32_t*>(C + (size_t)gm * 256 + gn)       = packh(c0, c1);
            *reinterpret_cast<uint32_t*>(C + (size_t)(gm + 8) * 256 + gn) = packh(c2, c3);
            colsum[2 * nt]     += c0 + c2;
            colsum[2 * nt + 1] += c1 + c3;
            colsq[2 * nt]      += c0 * c0 + c2 * c2;
            colsq[2 * nt + 1]  += c1 * c1 + c3 * c3;
        }
    }

    __syncthreads();                    // stage smem reusable now
    float* ssum = (float*)smem;         // 128 floats
    float* ssq  = ssum + 128;           // 128 floats
    ((float*)smem)[tid] = 0.f;          // zero 256 floats
    __syncthreads();
#pragma unroll
    for (int nt = 0; nt < 4; nt++) {
        int cl = wn * 32 + nt * 8 + 2 * (lane & 3);
        atomicAdd(&ssum[cl],     colsum[2 * nt]);
        atomicAdd(&ssum[cl + 1], colsum[2 * nt + 1]);
        atomicAdd(&ssq[cl],      colsq[2 * nt]);
        atomicAdd(&ssq[cl + 1],  colsq[2 * nt + 1]);
    }
    __syncthreads();
    if (tid < 128) {
        atomicAdd(&gsum[n0 + tid], ssum[tid]);
        atomicAdd(&gsq[n0 + tid],  ssq[tid]);
    }
}

__global__ void __launch_bounds__(256) gemm0_kernel(const float* __restrict__ b0) {
    gemm_body<K0_>(g_A, g_W0h, b0, g_y0, g_sum0, g_sq0);
}
__global__ void __launch_bounds__(256) gemm1k_kernel(const float* __restrict__ b1) {
    gemm_body<M0_>(g_Z, g_W1h, b1, g_y1, g_sum1, g_sq1);
}

// ---------------- kernel: finalize BN stats -> scale/shift ------------------
__global__ void finalize0_kernel(const float* __restrict__ gamma,
                                 const float* __restrict__ beta) {
    int c = threadIdx.x;
    float cnt = (float)MTOT;
    float mean = g_sum0[c] / cnt;
    float var = g_sq0[c] / cnt - mean * mean;
    float inv = rsqrtf(var + 1e-5f);
    float sc = gamma[c] * inv;
    g_scale0[c] = sc;
    g_shift0[c] = beta[c] - mean * sc;
}
__global__ void finalize1_kernel(const float* __restrict__ gamma,
                                 const float* __restrict__ beta) {
    int c = threadIdx.x;
    float cnt = (float)MTOT;
    float mean = g_sum1[c] / cnt;
    float var = g_sq1[c] / cnt - mean * mean;
    float inv = rsqrtf(var + 1e-5f);
    float sc = gamma[c] * inv;
    g_scale1[c] = sc;
    g_shift1[c] = beta[c] - mean * sc;
}

// ---------------- kernel: BN + ReLU on fp16 y0 -> fp16 Z --------------------
__global__ void bnrelu0_kernel() {
    size_t i4 = (size_t)blockIdx.x * 256 + threadIdx.x;   // group of 4 halves
    uint2 v = ((const uint2*)g_y0)[i4];
    __half2 h01 = *reinterpret_cast<__half2*>(&v.x);
    __half2 h23 = *reinterpret_cast<__half2*>(&v.y);
    int c = ((int)(i4 & 63)) * 4;                          // 64 groups per 256-ch row
    float x0 = fmaxf(__low2float(h01)  * g_scale0[c + 0] + g_shift0[c + 0], 0.f);
    float x1 = fmaxf(__high2float(h01) * g_scale0[c + 1] + g_shift0[c + 1], 0.f);
    float x2 = fmaxf(__low2float(h23)  * g_scale0[c + 2] + g_shift0[c + 2], 0.f);
    float x3 = fmaxf(__high2float(h23) * g_scale0[c + 3] + g_shift0[c + 3], 0.f);
    ((uint2*)g_Z)[i4] = make_uint2(packh(x0, x1), packh(x2, x3));
}

// ---------------- kernel: BN + ReLU + transpose -> out [B, M1, N] -----------
__global__ void bnrelu1_transpose_kernel(float* __restrict__ out) {
    __shared__ float tile[32][33];
    int b = blockIdx.z;
    int n0 = blockIdx.x * 32, o0 = blockIdx.y * 32;
    int tx = threadIdx.x, ty = threadIdx.y;
    float sc = g_scale1[o0 + tx];
    float sh = g_shift1[o0 + tx];
    const __half* ip = g_y1 + (size_t)b * N_ * M1_;
#pragma unroll
    for (int i = 0; i < 4; i++) {
        int r = ty + i * 8;
        float v = __half2float(ip[(size_t)(n0 + r) * M1_ + o0 + tx]);
        tile[r][tx] = fmaxf(v * sc + sh, 0.f);
    }
    __syncthreads();
    float* op = out + (size_t)b * M1_ * N_;
#pragma unroll
    for (int i = 0; i < 4; i++) {
        int r = ty + i * 8;
        op[(size_t)(o0 + r) * N_ + n0 + tx] = tile[tx][r];
    }
}

// ---------------- launch ----------------------------------------------------
extern "C" void kernel_launch(void* const* d_in, const int* in_sizes, int n_in,
                              void* d_out, int out_size) {
    const float* xyz1 = (const float*)d_in[0];
    const float* xyz2 = (const float*)d_in[1];
    const float* p1   = (const float*)d_in[2];
    const float* p2   = (const float*)d_in[3];
    const float* w0   = (const float*)d_in[4];
    const float* b0   = (const float*)d_in[5];
    const float* g0   = (const float*)d_in[6];
    const float* be0  = (const float*)d_in[7];
    const float* w1   = (const float*)d_in[8];
    const float* b1   = (const float*)d_in[9];
    const float* g1   = (const float*)d_in[10];
    const float* be1  = (const float*)d_in[11];
    float* out = (float*)d_out;

    prep_kernel<<<512, 256>>>(w0, w1);
    transpose_p1_kernel<<<dim3(N_ / 32, C1_ / 32, B_), dim3(32, 8)>>>(p1);
    transpose_p2_kernel<<<dim3(S_ / 32, C2_ / 32, B_), dim3(32, 8)>>>(p2);
    knn_kernel<<<dim3(N_ / 128, B_), 512>>>(xyz1, xyz2);
    gather_kernel<<<dim3(N_ / 8, B_), 256>>>();

    gemm0_kernel<<<dim3(M0_ / 128, MTOT / 128), 256>>>(b0);
    finalize0_kernel<<<1, 256>>>(g0, be0);
    bnrelu0_kernel<<<(unsigned)((size_t)MTOT * M0_ / 4 / 256), 256>>>();

    gemm1k_kernel<<<dim3(M1_ / 128, MTOT / 128), 256>>>(b1);
    finalize1_kernel<<<1, 256>>>(g1, be1);
    bnrelu1_transpose_kernel<<<dim3(N_ / 32, M1_ / 32, B_), dim3(32, 8)>>>(out);
}

// round 17
// speedup vs baseline: 2.5983x; 1.0648x over previous
#include <cuda_runtime.h>
#include <cuda_fp16.h>
#include <cstdint>
#include <cstddef>

// Problem dims (fixed by the dataset)
#define B_   16
#define N_   4096
#define S_   1024
#define C1_  256
#define C2_  256
#define K0_  512      // C1+C2
#define M0_  256
#define M1_  256
#define MTOT (B_*N_)  // 65536 rows (b*N+n)

// ---------------- scratch (static device globals; no cudaMalloc allowed) ----
__device__ __align__(16) __half g_A[(size_t)MTOT * K0_];    // 64 MB concat activations fp16
__device__ __align__(16) __half g_Z[(size_t)MTOT * M0_];    // 32 MB layer-1 input fp16
__device__ __align__(16) __half g_W0h[(size_t)M0_ * K0_];
__device__ __align__(16) __half g_W1h[(size_t)M1_ * M0_];
__device__ __align__(16) __half g_y0[(size_t)MTOT * M0_];   // layer-0 pre-BN fp16
__device__ __align__(16) __half g_y1[(size_t)MTOT * M1_];   // layer-1 pre-BN fp16
__device__ float g_p2t[(size_t)B_ * S_ * C2_];    // [B, S, C2]  transposed points2
__device__ int   g_idx[(size_t)B_ * N_ * 3];
__device__ float g_w[(size_t)B_ * N_ * 3];
__device__ float g_sum0[M0_], g_sq0[M0_], g_sum1[M1_], g_sq1[M1_];

// ---------------- small helpers ---------------------------------------------
static __device__ __forceinline__ uint32_t sm32(const void* p) {
    return (uint32_t)__cvta_generic_to_shared(p);
}
static __device__ __forceinline__ uint32_t packh(float a, float b) {
    __half2 t = __floats2half2_rn(a, b);
    return *reinterpret_cast<uint32_t*>(&t);
}
static __device__ __forceinline__ void cpa16(uint32_t dst, const void* src) {
    asm volatile("cp.async.cg.shared.global [%0], [%1], 16;" :: "r"(dst), "l"(src));
}
static __device__ __forceinline__ void cp_commit() {
    asm volatile("cp.async.commit_group;" ::: "memory");
}
template <int n>
static __device__ __forceinline__ void cp_wait() {
    asm volatile("cp.async.wait_group %0;" :: "n"(n) : "memory");
}
// ldmatrix x4 (b16, non-transposed)
static __device__ __forceinline__ void ldmx4(uint32_t r[4], uint32_t addr) {
    asm volatile("ldmatrix.sync.aligned.m8n8.x4.shared.b16 {%0,%1,%2,%3}, [%4];"
                 : "=r"(r[0]), "=r"(r[1]), "=r"(r[2]), "=r"(r[3]) : "r"(addr));
}
// HMMA m16n8k16 fp16 -> f32 accumulate (base sm_80+ PTX, legal on compute_103)
static __device__ __forceinline__ void mma16816(float c[4], const uint32_t a[4],
                                                const uint32_t b[2]) {
    asm volatile(
        "mma.sync.aligned.m16n8k16.row.col.f32.f16.f16.f32 "
        "{%0,%1,%2,%3}, {%4,%5,%6,%7}, {%8,%9}, {%0,%1,%2,%3};"
        : "+f"(c[0]), "+f"(c[1]), "+f"(c[2]), "+f"(c[3])
        : "r"(a[0]), "r"(a[1]), "r"(a[2]), "r"(a[3]), "r"(b[0]), "r"(b[1]));
}
// swizzle for 32B rows (8-row atom spans 256B): XOR bit4 with bit7
static __device__ __forceinline__ uint32_t swz(uint32_t off) {
    return off ^ ((off >> 3) & 0x10);
}

// ---------------- kernel: prep (zero stats + both weight converts) ----------
__global__ void prep_kernel(const float* __restrict__ w0,
                            const float* __restrict__ w1) {
    int i = blockIdx.x * 256 + threadIdx.x;      // grid 512 blocks -> 131072
    if (i < 256) {
        g_sum0[i] = 0.f; g_sq0[i] = 0.f;
        g_sum1[i] = 0.f; g_sq1[i] = 0.f;
    }
    if (i < M0_ * K0_) g_W0h[i] = __float2half_rn(w0[i]);
    if (i < M1_ * M0_) g_W1h[i] = __float2half_rn(w1[i]);
}

// ---------------- kernel: transpose points1 [B,C1,N] -> g_A[:, 0:256] -------
__global__ void transpose_p1_kernel(const float* __restrict__ p1) {
    __shared__ float tile[32][33];               // tile[c][n]
    int b = blockIdx.z;
    int n0 = blockIdx.x * 32, c0 = blockIdx.y * 32;
    int tx = threadIdx.x, ty = threadIdx.y;      // (32, 8)
    const float* ip = p1 + (size_t)b * C1_ * N_;
#pragma unroll
    for (int i = 0; i < 4; i++) {
        int r = ty + i * 8;
        tile[r][tx] = ip[(size_t)(c0 + r) * N_ + n0 + tx];
    }
    __syncthreads();
    int t = ty * 32 + tx;                        // 0..255
    int cp = t & 15;                             // channel pair 0..15
    int r0r = t >> 4;                            // 0..15
    size_t rb = (size_t)b * N_;
#pragma unroll
    for (int i = 0; i < 2; i++) {
        int row = r0r + i * 16;
        uint32_t v = packh(tile[2 * cp][row], tile[2 * cp + 1][row]);
        *reinterpret_cast<uint32_t*>(g_A + (rb + n0 + row) * K0_ + c0 + 2 * cp) = v;
    }
}

// ---------------- kernel: transpose points2 [B,C2,S] -> p2t [B,S,C2] --------
__global__ void transpose_p2_kernel(const float* __restrict__ p2) {
    __shared__ float tile[32][33];
    int b = blockIdx.z;
    int s0 = blockIdx.x * 32, c0 = blockIdx.y * 32;
    int tx = threadIdx.x, ty = threadIdx.y;
    const float* ip = p2 + (size_t)b * C2_ * S_;
    float* op = g_p2t + (size_t)b * S_ * C2_;
#pragma unroll
    for (int i = 0; i < 4; i++) {
        int r = ty + i * 8;
        tile[r][tx] = ip[(size_t)(c0 + r) * S_ + s0 + tx];
    }
    __syncthreads();
#pragma unroll
    for (int i = 0; i < 4; i++) {
        int r = ty + i * 8;
        op[(size_t)(s0 + r) * C2_ + c0 + tx] = tile[tx][r];
    }
}

// ---------------- kernel: 3-NN, S split 4-way across threads ----------------
// 512 threads = 128 points x 4 S-quarters; each thread scans 256 candidates
// (2 chains of 128), partial top-3 merged through smem.
__global__ void __launch_bounds__(512) knn_kernel(const float* __restrict__ xyz1,
                                                  const float* __restrict__ xyz2) {
    __shared__ float4 s4[S_];
    __shared__ float2 mrg[128][9];               // halves 1..3 publish top-3
    int b = blockIdx.y;
    const float* x2 = xyz2 + (size_t)b * 3 * S_;
    for (int j = threadIdx.x; j < S_; j += 512) {
        float a = x2[j], c = x2[S_ + j], d = x2[2 * S_ + j];
        s4[j] = make_float4(a, c, d, a * a + c * c + d * d);
    }
    __syncthreads();

    int tl = threadIdx.x & 127;                  // point within block
    int h  = threadIdx.x >> 7;                   // S-quarter 0..3
    int n  = blockIdx.x * 128 + tl;
    const float* x1 = xyz1 + (size_t)b * 3 * N_;
    float px = x1[n], py = x1[N_ + n], pz = x1[2 * N_ + n];
    float n1 = px * px + py * py + pz * pz;

    float cd0[2], cd1[2], cd2[2];
    int   ci0[2], ci1[2], ci2[2];
#pragma unroll
    for (int c = 0; c < 2; c++) {
        cd0[c] = cd1[c] = cd2[c] = 1e30f;
        ci0[c] = ci1[c] = ci2[c] = 0;
    }
    int sb = h * 256;
#pragma unroll 4
    for (int t = 0; t < 128; t++) {
#pragma unroll
        for (int c = 0; c < 2; c++) {
            int s = sb + t + c * 128;
            float4 w = s4[s];
            float dot = px * w.x + py * w.y + pz * w.z;
            float d = n1 + w.w - 2.f * dot;
            if (d < cd2[c]) {
                if (d < cd1[c]) {
                    cd2[c] = cd1[c]; ci2[c] = ci1[c];
                    if (d < cd0[c]) { cd1[c] = cd0[c]; ci1[c] = ci0[c]; cd0[c] = d; ci0[c] = s; }
                    else            { cd1[c] = d;      ci1[c] = s; }
                } else { cd2[c] = d; ci2[c] = s; }
            }
        }
    }
    // merge this thread's 2 chains (insert in increasing-s order)
    float d0 = 1e30f, d1 = 1e30f, d2 = 1e30f;
    int i0 = 0, i1 = 0, i2 = 0;
    auto ins = [&](float d, int i) {
        if (d < d2) {
            if (d < d1) {
                d2 = d1; i2 = i1;
                if (d < d0) { d1 = d0; i1 = i0; d0 = d; i0 = i; }
                else        { d1 = d;  i1 = i; }
            } else { d2 = d; i2 = i; }
        }
    };
#pragma unroll
    for (int c = 0; c < 2; c++) { ins(cd0[c], ci0[c]); ins(cd1[c], ci1[c]); ins(cd2[c], ci2[c]); }

    if (h) {
        int o = 3 * (h - 1);
        mrg[tl][o]     = make_float2(d0, __int_as_float(i0));
        mrg[tl][o + 1] = make_float2(d1, __int_as_float(i1));
        mrg[tl][o + 2] = make_float2(d2, __int_as_float(i2));
    }
    __syncthreads();
    if (h == 0) {
#pragma unroll
        for (int q = 0; q < 9; q++) {
            float2 v = mrg[tl][q];
            ins(v.x, __float_as_int(v.y));
        }
        float r0 = 1.f / (d0 + 1e-8f);
        float r1 = 1.f / (d1 + 1e-8f);
        float r2 = 1.f / (d2 + 1e-8f);
        float rs = r0 + r1 + r2;
        size_t base = ((size_t)b * N_ + n) * 3;
        g_idx[base] = i0; g_idx[base + 1] = i1; g_idx[base + 2] = i2;
        g_w[base] = r0 / rs; g_w[base + 1] = r1 / rs; g_w[base + 2] = r2 / rs;
    }
}

// ---------------- kernel: weighted gather -> g_A[:, 256:512] ----------------
__global__ void gather_kernel() {
    int b = blockIdx.y;
    int warp = threadIdx.x >> 5, lane = threadIdx.x & 31;
    int n = blockIdx.x * 8 + warp;
    size_t base = ((size_t)b * N_ + n) * 3;
    int i0 = g_idx[base], i1 = g_idx[base + 1], i2 = g_idx[base + 2];
    float w0 = g_w[base], w1 = g_w[base + 1], w2 = g_w[base + 2];
    const float4* r0 = (const float4*)(g_p2t + ((size_t)b * S_ + i0) * C2_);
    const float4* r1 = (const float4*)(g_p2t + ((size_t)b * S_ + i1) * C2_);
    const float4* r2 = (const float4*)(g_p2t + ((size_t)b * S_ + i2) * C2_);
    size_t rowe = ((size_t)b * N_ + n) * K0_ + C1_;
#pragma unroll
    for (int t = 0; t < 2; t++) {
        int c = lane + t * 32;                 // 64 float4 per 256-ch half
        float4 a = r0[c], bb = r1[c], cc = r2[c];
        float ox = w0 * a.x + w1 * bb.x + w2 * cc.x;
        float oy = w0 * a.y + w1 * bb.y + w2 * cc.y;
        float oz = w0 * a.z + w1 * bb.z + w2 * cc.z;
        float ow = w0 * a.w + w1 * bb.w + w2 * cc.w;
        *reinterpret_cast<uint2*>(g_A + rowe + 4 * c) =
            make_uint2(packh(ox, oy), packh(oz, ow));
    }
}

// ---------------- HMMA fp16 GEMM: C(fp16) = A[M,K]*W[256,K]^T + bias --------
// CTA tile 128x128, 8 warps (2x4), warp tile 64x32, BK=16.
// 4-stage cp.async pipeline with a SINGLE __syncthreads per k-step:
// at iteration c the buffer (c+3)&3 (last consumed at c-1) is refilled right
// after the top-of-loop barrier, overlapping the MMA bundle.
// Grid (n, m): consecutive CTAs share the A tile -> L2 reuse.
// Accumulates per-output-channel sum/sumsq (BN training stats) in fp32.
template <int KDIM>
static __device__ __forceinline__ void gemm_body(
    const __half* __restrict__ A, const __half* __restrict__ Wh,
    const float* __restrict__ bias, __half* __restrict__ C,
    float* __restrict__ gsum, float* __restrict__ gsq) {
    constexpr int NC = KDIM / 16;              // 32 or 16 k-steps
    __shared__ __align__(1024) char smem[4 * 8192];    // 4 stages x (A|W 4KB each)

    int tid = threadIdx.x, lane = tid & 31, wid = tid >> 5;
    int wm = wid & 1, wn = wid >> 1;           // 2 x 4 warp grid
    int n0 = blockIdx.x * 128, m0 = blockIdx.y * 128;

    const char* pA = (const char*)A;
    const char* pW = (const char*)Wh;
    const size_t rowb = (size_t)KDIM * 2;      // bytes per gmem row

    uint32_t smb = sm32(smem);

    // --- per-thread cp.async assignments (2 x 16B per stage) ---
    auto load_stage = [&](int c, int st) {
        uint32_t sb = smb + st * 8192;
        int kb = c * 32;                       // byte offset of k16 chunk
#pragma unroll
        for (int i = 0; i < 2; i++) {
            int idx = tid + i * 256;
            int part = idx >> 8, v = idx & 255;
            int row = v >> 1, seg = v & 1;
            uint32_t off = (uint32_t)(row * 32 + seg * 16);
            uint32_t dst = sb + part * 4096 + swz(off);
            if (part == 0)
                cpa16(dst, pA + (size_t)(m0 + row) * rowb + kb + seg * 16);
            else
                cpa16(dst, pW + (size_t)(n0 + row) * rowb + kb + seg * 16);
        }
    };

    // --- ldmatrix per-lane offsets (within a 4KB part region) ---
    uint32_t aoff[4], boff[2];
    {
        int arow = wm * 64 + (lane & 15);
        int akc = (lane >> 4) * 8;             // lanes 16-31 read k+8 matrices
#pragma unroll
        for (int mt = 0; mt < 4; mt++)
            aoff[mt] = swz((uint32_t)((arow + mt * 16) * 32 + akc * 2));
        int brow = wn * 32 + ((lane >> 4) << 3) + (lane & 7);
        int bkc = ((lane >> 3) & 1) * 8;
#pragma unroll
        for (int nt2 = 0; nt2 < 2; nt2++)
            boff[nt2] = swz((uint32_t)((brow + nt2 * 16) * 32 + bkc * 2));
    }

    float acc[4][4][4];
#pragma unroll
    for (int i = 0; i < 4; i++)
#pragma unroll
        for (int j = 0; j < 4; j++)
#pragma unroll
            for (int q = 0; q < 4; q++) acc[i][j][q] = 0.f;

    load_stage(0, 0); cp_commit();
    load_stage(1, 1); cp_commit();
    load_stage(2, 2); cp_commit();

#pragma unroll 1
    for (int c = 0; c < NC; c++) {
        int st = c & 3;
        if (c < NC - 2)       cp_wait<2>();
        else if (c == NC - 2) cp_wait<1>();
        else                  cp_wait<0>();
        __syncthreads();
        if (c + 3 < NC) { load_stage(c + 3, (c + 3) & 3); cp_commit(); }

        uint32_t sb = smb + st * 8192;
        uint32_t ah[4][4], wh[4][2];
#pragma unroll
        for (int mt = 0; mt < 4; mt++) ldmx4(ah[mt], sb + aoff[mt]);
#pragma unroll
        for (int nt2 = 0; nt2 < 2; nt2++) {
            uint32_t r[4];
            ldmx4(r, sb + 4096 + boff[nt2]);
            wh[2 * nt2][0] = r[0]; wh[2 * nt2][1] = r[1];
            wh[2 * nt2 + 1][0] = r[2]; wh[2 * nt2 + 1][1] = r[3];
        }
#pragma unroll
        for (int mt = 0; mt < 4; mt++)
#pragma unroll
            for (int nt = 0; nt < 4; nt++)
                mma16816(acc[mt][nt], ah[mt], wh[nt]);
    }

    // ---- epilogue: bias, fp16 store, BN stats (from fp32 values) ----
    float bv[8];
#pragma unroll
    for (int nt = 0; nt < 4; nt++) {
        int gn = n0 + wn * 32 + nt * 8 + 2 * (lane & 3);
        bv[2 * nt] = bias[gn];
        bv[2 * nt + 1] = bias[gn + 1];
    }
    float colsum[8], colsq[8];
#pragma unroll
    for (int j = 0; j < 8; j++) { colsum[j] = 0.f; colsq[j] = 0.f; }

#pragma unroll
    for (int mt = 0; mt < 4; mt++) {
        int gm = m0 + wm * 64 + mt * 16 + (lane >> 2);
#pragma unroll
        for (int nt = 0; nt < 4; nt++) {
            int gn = n0 + wn * 32 + nt * 8 + 2 * (lane & 3);
            float c0 = acc[mt][nt][0] + bv[2 * nt];
            float c1 = acc[mt][nt][1] + bv[2 * nt + 1];
            float c2 = acc[mt][nt][2] + bv[2 * nt];
            float c3 = acc[mt][nt][3] + bv[2 * nt + 1];
            *reinterpret_cast<uint32_t*>(C + (size_t)gm * 256 + gn)       = packh(c0, c1);
            *reinterpret_cast<uint32_t*>(C + (size_t)(gm + 8) * 256 + gn) = packh(c2, c3);
            colsum[2 * nt]     += c0 + c2;
            colsum[2 * nt + 1] += c1 + c3;
            colsq[2 * nt]      += c0 * c0 + c2 * c2;
            colsq[2 * nt + 1]  += c1 * c1 + c3 * c3;
        }
    }

    __syncthreads();                    // all loads complete; stage smem reusable
    float* ssum = (float*)smem;         // 128 floats
    float* ssq  = ssum + 128;           // 128 floats
    ((float*)smem)[tid] = 0.f;          // zero 256 floats
    __syncthreads();
#pragma unroll
    for (int nt = 0; nt < 4; nt++) {
        int cl = wn * 32 + nt * 8 + 2 * (lane & 3);
        atomicAdd(&ssum[cl],     colsum[2 * nt]);
        atomicAdd(&ssum[cl + 1], colsum[2 * nt + 1]);
        atomicAdd(&ssq[cl],      colsq[2 * nt]);
        atomicAdd(&ssq[cl + 1],  colsq[2 * nt + 1]);
    }
    __syncthreads();
    if (tid < 128) {
        atomicAdd(&gsum[n0 + tid], ssum[tid]);
        atomicAdd(&gsq[n0 + tid],  ssq[tid]);
    }
}

__global__ void __launch_bounds__(256) gemm0_kernel(const float* __restrict__ b0) {
    gemm_body<K0_>(g_A, g_W0h, b0, g_y0, g_sum0, g_sq0);
}
__global__ void __launch_bounds__(256) gemm1k_kernel(const float* __restrict__ b1) {
    gemm_body<M0_>(g_Z, g_W1h, b1, g_y1, g_sum1, g_sq1);
}

// ---------------- kernel: BN(finalized in-block) + ReLU on y0 -> fp16 Z -----
__global__ void bnrelu0_kernel(const float* __restrict__ gamma,
                               const float* __restrict__ beta) {
    __shared__ float ssc[256], ssh[256];
    int tid = threadIdx.x;
    {   // per-block BN finalize (one rsqrt per thread)
        float cnt = (float)MTOT;
        float mean = g_sum0[tid] / cnt;
        float var = g_sq0[tid] / cnt - mean * mean;
        float sc = gamma[tid] * rsqrtf(var + 1e-5f);
        ssc[tid] = sc;
        ssh[tid] = beta[tid] - mean * sc;
    }
    __syncthreads();
    size_t i4 = (size_t)blockIdx.x * 256 + tid;            // group of 4 halves
    uint2 v = ((const uint2*)g_y0)[i4];
    __half2 h01 = *reinterpret_cast<__half2*>(&v.x);
    __half2 h23 = *reinterpret_cast<__half2*>(&v.y);
    int c = ((int)(i4 & 63)) * 4;                          // 64 groups per 256-ch row
    float x0 = fmaxf(__low2float(h01)  * ssc[c + 0] + ssh[c + 0], 0.f);
    float x1 = fmaxf(__high2float(h01) * ssc[c + 1] + ssh[c + 1], 0.f);
    float x2 = fmaxf(__low2float(h23)  * ssc[c + 2] + ssh[c + 2], 0.f);
    float x3 = fmaxf(__high2float(h23) * ssc[c + 3] + ssh[c + 3], 0.f);
    ((uint2*)g_Z)[i4] = make_uint2(packh(x0, x1), packh(x2, x3));
}

// ---------------- kernel: BN(finalized) + ReLU + transpose -> out [B,M1,N] --
__global__ void bnrelu1_transpose_kernel(float* __restrict__ out,
                                         const float* __restrict__ gamma,
                                         const float* __restrict__ beta) {
    __shared__ float tile[32][33];
    __shared__ float ssc[32], ssh[32];
    int b = blockIdx.z;
    int n0 = blockIdx.x * 32, o0 = blockIdx.y * 32;
    int tx = threadIdx.x, ty = threadIdx.y;
    if (ty == 0) {
        int ch = o0 + tx;
        float cnt = (float)MTOT;
        float mean = g_sum1[ch] / cnt;
        float var = g_sq1[ch] / cnt - mean * mean;
        float sc = gamma[ch] * rsqrtf(var + 1e-5f);
        ssc[tx] = sc;
        ssh[tx] = beta[ch] - mean * sc;
    }
    __syncthreads();
    float sc = ssc[tx], sh = ssh[tx];
    const __half* ip = g_y1 + (size_t)b * N_ * M1_;
#pragma unroll
    for (int i = 0; i < 4; i++) {
        int r = ty + i * 8;
        float v = __half2float(ip[(size_t)(n0 + r) * M1_ + o0 + tx]);
        tile[r][tx] = fmaxf(v * sc + sh, 0.f);
    }
    __syncthreads();
    float* op = out + (size_t)b * M1_ * N_;
#pragma unroll
    for (int i = 0; i < 4; i++) {
        int r = ty + i * 8;
        op[(size_t)(o0 + r) * N_ + n0 + tx] = tile[tx][r];
    }
}

// ---------------- launch ----------------------------------------------------
extern "C" void kernel_launch(void* const* d_in, const int* in_sizes, int n_in,
                              void* d_out, int out_size) {
    const float* xyz1 = (const float*)d_in[0];
    const float* xyz2 = (const float*)d_in[1];
    const float* p1   = (const float*)d_in[2];
    const float* p2   = (const float*)d_in[3];
    const float* w0   = (const float*)d_in[4];
    const float* b0   = (const float*)d_in[5];
    const float* g0   = (const float*)d_in[6];
    const float* be0  = (const float*)d_in[7];
    const float* w1   = (const float*)d_in[8];
    const float* b1   = (const float*)d_in[9];
    const float* g1   = (const float*)d_in[10];
    const float* be1  = (const float*)d_in[11];
    float* out = (float*)d_out;

    prep_kernel<<<512, 256>>>(w0, w1);
    transpose_p1_kernel<<<dim3(N_ / 32, C1_ / 32, B_), dim3(32, 8)>>>(p1);
    transpose_p2_kernel<<<dim3(S_ / 32, C2_ / 32, B_), dim3(32, 8)>>>(p2);
    knn_kernel<<<dim3(N_ / 128, B_), 512>>>(xyz1, xyz2);
    gather_kernel<<<dim3(N_ / 8, B_), 256>>>();

    gemm0_kernel<<<dim3(M0_ / 128, MTOT / 128), 256>>>(b0);
    bnrelu0_kernel<<<(unsigned)((size_t)MTOT * M0_ / 4 / 256), 256>>>(g0, be0);

    gemm1k_kernel<<<dim3(M1_ / 128, MTOT / 128), 256>>>(b1);
    bnrelu1_transpose_kernel<<<dim3(N_ / 32, M1_ / 32, B_), dim3(32, 8)>>>(out, g1, be1);
}